// round 12
// baseline (speedup 1.0000x reference)
#include <cuda_runtime.h>
#include <cuda_bf16.h>
#include <cstdint>
#include <cstddef>

#define BB 4
#define SS 2048
#define DD 1024
#define HH 16
#define MTOK (BB*SS)
#define NQKV (3*DD)
#define QSCALE 0.1803368801111204f   // 0.125 * log2(e)

// ---------------- scratch (__device__ globals; allocs forbidden) ----------
__device__ __nv_bfloat16 g_xqh[MTOK*DD], g_xql[MTOK*DD];
__device__ __nv_bfloat16 g_xkh[MTOK*DD], g_xkl[MTOK*DD];
__device__ __nv_bfloat16 g_xvh[MTOK*DD], g_xvl[MTOK*DD];
__device__ __nv_bfloat16 g_wqkvh[3*DD*DD], g_wqkvl[3*DD*DD];
__device__ __nv_bfloat16 g_woh[DD*DD], g_wol[DD*DD];
__device__ __nv_bfloat16 g_qkvh[(size_t)MTOK*NQKV], g_qkvl[(size_t)MTOK*NQKV];
__device__ __nv_bfloat16 g_oh[MTOK*DD], g_ol[MTOK*DD];
__device__ uint32_t g_mbits[(size_t)BB*SS*(SS/32)];

// ---------------- helpers --------------------------------------------------
__device__ __forceinline__ uint32_t smem_u32(const void* p) {
    return (uint32_t)__cvta_generic_to_shared(p);
}
__device__ __forceinline__ void mma16816(float* c, const uint32_t* a, const uint32_t* b) {
    asm volatile(
        "mma.sync.aligned.m16n8k16.row.col.f32.bf16.bf16.f32 "
        "{%0,%1,%2,%3},{%4,%5,%6,%7},{%8,%9},{%0,%1,%2,%3};"
        : "+f"(c[0]), "+f"(c[1]), "+f"(c[2]), "+f"(c[3])
        : "r"(a[0]), "r"(a[1]), "r"(a[2]), "r"(a[3]), "r"(b[0]), "r"(b[1]));
}
__device__ __forceinline__ void ldsm_x4(uint32_t* r, const void* p) {
    uint32_t a = smem_u32(p);
    asm volatile("ldmatrix.sync.aligned.m8n8.x4.shared.b16 {%0,%1,%2,%3},[%4];"
                 : "=r"(r[0]), "=r"(r[1]), "=r"(r[2]), "=r"(r[3]) : "r"(a));
}
__device__ __forceinline__ void ldsm_x4t(uint32_t* r, const void* p) {
    uint32_t a = smem_u32(p);
    asm volatile("ldmatrix.sync.aligned.m8n8.x4.trans.shared.b16 {%0,%1,%2,%3},[%4];"
                 : "=r"(r[0]), "=r"(r[1]), "=r"(r[2]), "=r"(r[3]) : "r"(a));
}
__device__ __forceinline__ void split2(float f0, float f1, uint32_t& hi, uint32_t& lo) {
    __nv_bfloat162 h = __floats2bfloat162_rn(f0, f1);
    float r0 = f0 - __bfloat162float(h.x);
    float r1 = f1 - __bfloat162float(h.y);
    hi = *reinterpret_cast<uint32_t*>(&h);
    __nv_bfloat162 l = __floats2bfloat162_rn(r0, r1);
    lo = *reinterpret_cast<uint32_t*>(&l);
}
__device__ __forceinline__ void cp16(void* s, const void* g) {
    uint32_t sa = smem_u32(s);
    asm volatile("cp.async.cg.shared.global [%0], [%1], 16;" :: "r"(sa), "l"(g));
}
#define CP_COMMIT() asm volatile("cp.async.commit_group;" ::: "memory")
#define CP_WAIT(n)  asm volatile("cp.async.wait_group %0;" :: "n"(n) : "memory")

// ---------------- prepass kernels ------------------------------------------
// input split: 4 float4 per thread (MLP=4)
__global__ void split3_kernel(const float4* __restrict__ x0, const float4* __restrict__ x1,
                              const float4* __restrict__ x2,
                              uint2* __restrict__ h0, uint2* __restrict__ l0,
                              uint2* __restrict__ h1, uint2* __restrict__ l1,
                              uint2* __restrict__ h2, uint2* __restrict__ l2, int n4) {
    int base = blockIdx.x * 1024 + threadIdx.x;
    const float4* x = (blockIdx.y == 0) ? x0 : (blockIdx.y == 1) ? x1 : x2;
    uint2* h = (blockIdx.y == 0) ? h0 : (blockIdx.y == 1) ? h1 : h2;
    uint2* l = (blockIdx.y == 0) ? l0 : (blockIdx.y == 1) ? l1 : l2;
    float4 v[4];
#pragma unroll
    for (int r = 0; r < 4; ++r) v[r] = x[base + r * 256];
#pragma unroll
    for (int r = 0; r < 4; ++r) {
        uint2 hh, ll;
        split2(v[r].x, v[r].y, hh.x, ll.x);
        split2(v[r].z, v[r].w, hh.y, ll.y);
        h[base + r * 256] = hh;
        l[base + r * 256] = ll;
    }
}
__global__ void splitw_kernel(const float4* __restrict__ wq, const float4* __restrict__ wk,
                              const float4* __restrict__ wv, const float4* __restrict__ wo,
                              uint2* __restrict__ qkvh, uint2* __restrict__ qkvl,
                              uint2* __restrict__ woh, uint2* __restrict__ wol, int n4) {
    int i = blockIdx.x * 256 + threadIdx.x;
    if (i >= n4) return;
    int y = blockIdx.y;
    const float4* src = (y == 0) ? wq : (y == 1) ? wk : (y == 2) ? wv : wo;
    float4 v = src[i];
    if (y == 0) { v.x *= QSCALE; v.y *= QSCALE; v.z *= QSCALE; v.w *= QSCALE; }
    uint2 hh, ll;
    split2(v.x, v.y, hh.x, ll.x);
    split2(v.z, v.w, hh.y, ll.y);
    uint2* h = (y < 3) ? (qkvh + (size_t)y * n4) : woh;
    uint2* l = (y < 3) ? (qkvl + (size_t)y * n4) : wol;
    h[i] = hh; l[i] = ll;
}
__global__ void maskbits_kernel(const int* __restrict__ m, uint32_t* __restrict__ bits) {
    size_t w = (size_t)blockIdx.x * 8 + (threadIdx.x >> 5);
    int lane = threadIdx.x & 31;
    const int* p = m + w * 128;
    int v0 = p[lane], v1 = p[lane + 32], v2 = p[lane + 64], v3 = p[lane + 96];
    uint32_t b0 = __ballot_sync(0xffffffffu, v0 != 0);
    uint32_t b1 = __ballot_sync(0xffffffffu, v1 != 0);
    uint32_t b2 = __ballot_sync(0xffffffffu, v2 != 0);
    uint32_t b3 = __ballot_sync(0xffffffffu, v3 != 0);
    if (lane == 0) { bits[w*4] = b0; bits[w*4+1] = b1; bits[w*4+2] = b2; bits[w*4+3] = b3; }
}

// ---------------- GEMM: 128x128 tile, 2 CTAs/SM, 2-stage, gap-4 mma order ---
#define GST 40
#define G_AH 0
#define G_AL (128*GST)
#define G_WH (2*128*GST)
#define G_WL (3*128*GST)
#define GSTAGE (4*128*GST)

__global__ __launch_bounds__(256, 2) void gemm_mma(
    const __nv_bfloat16* __restrict__ A0h, const __nv_bfloat16* __restrict__ A0l,
    const __nv_bfloat16* __restrict__ A1h, const __nv_bfloat16* __restrict__ A1l,
    const __nv_bfloat16* __restrict__ A2h, const __nv_bfloat16* __restrict__ A2l,
    const __nv_bfloat16* __restrict__ Wh, const __nv_bfloat16* __restrict__ Wl,
    float* __restrict__ Cf, __nv_bfloat16* __restrict__ Ch, __nv_bfloat16* __restrict__ Cl,
    int N, int K, int split_out)
{
    extern __shared__ __align__(16) __nv_bfloat16 sg[];

    const int tid = threadIdx.x, lane = tid & 31, w = tid >> 5;
    const int g = lane >> 2, t4 = lane & 3, l15 = lane & 15;
    const int m0 = (w >> 2) * 64, n0 = (w & 3) * 32;
    const int bm = blockIdx.y * 128, bn = blockIdx.x * 128;

    const int sel = bn >> 10;
    const __nv_bfloat16* Ah = (sel == 0) ? A0h : (sel == 1) ? A1h : A2h;
    const __nv_bfloat16* Al = (sel == 0) ? A0l : (sel == 1) ? A1l : A2l;

    const __nv_bfloat16* pAh = Ah + (size_t)bm * K;
    const __nv_bfloat16* pAl = Al + (size_t)bm * K;
    const __nv_bfloat16* pWh = Wh + (size_t)bn * K;
    const __nv_bfloat16* pWl = Wl + (size_t)bn * K;

    auto stage = [&](int buf, int k0) {
        __nv_bfloat16* st = sg + buf * GSTAGE;
#pragma unroll
        for (int it = 0; it < 8; ++it) {
            int c = it * 256 + tid;
            int mat = c >> 9, r = (c >> 2) & 127, u = c & 3;
            const __nv_bfloat16* src =
                (mat == 0 ? pAh : mat == 1 ? pAl : mat == 2 ? pWh : pWl)
                + (size_t)r * K + k0 + u * 8;
            cp16(st + mat * (128 * GST) + r * GST + u * 8, src);
        }
    };

    float acc[4][4][4];
#pragma unroll
    for (int i = 0; i < 4; ++i)
#pragma unroll
        for (int j = 0; j < 4; ++j)
#pragma unroll
            for (int c = 0; c < 4; ++c) acc[i][j][c] = 0.f;

    const int NST = K / 32;
    stage(0, 0); CP_COMMIT();

    for (int kt = 0; kt < NST; ++kt) {
        const int buf = kt & 1;
        if (kt + 1 < NST) { stage(buf ^ 1, (kt + 1) * 32); CP_COMMIT(); CP_WAIT(1); }
        else CP_WAIT(0);
        __syncthreads();

        const __nv_bfloat16* st = sg + buf * GSTAGE;
#pragma unroll
        for (int ks = 0; ks < 32; ks += 16) {
            uint32_t wh[2][4], wl[2][4];
            {
                const int ro0 = (n0 + l15) * GST + ks + (lane >> 4) * 8;
                const int ro1 = (n0 + 16 + l15) * GST + ks + (lane >> 4) * 8;
                ldsm_x4(wh[0], st + G_WH + ro0);
                ldsm_x4(wl[0], st + G_WL + ro0);
                ldsm_x4(wh[1], st + G_WH + ro1);
                ldsm_x4(wl[1], st + G_WL + ro1);
            }
            uint32_t ah[2][4], al[2][4];
            {
                const int ro = (m0 + l15) * GST + ks + (lane >> 4) * 8;
                ldsm_x4(ah[0], st + G_AH + ro);
                ldsm_x4(al[0], st + G_AL + ro);
            }
#pragma unroll
            for (int mt = 0; mt < 4; ++mt) {
                const int cur = mt & 1;
                if (mt < 3) {
                    const int ro = (m0 + (mt + 1) * 16 + l15) * GST + ks + (lane >> 4) * 8;
                    ldsm_x4(ah[cur ^ 1], st + G_AH + ro);
                    ldsm_x4(al[cur ^ 1], st + G_AL + ro);
                }
                uint32_t bhe0[2] = {wh[0][0], wh[0][2]}, bho0[2] = {wh[0][1], wh[0][3]};
                uint32_t bhe1[2] = {wh[1][0], wh[1][2]}, bho1[2] = {wh[1][1], wh[1][3]};
                uint32_t ble0[2] = {wl[0][0], wl[0][2]}, blo0[2] = {wl[0][1], wl[0][3]};
                uint32_t ble1[2] = {wl[1][0], wl[1][2]}, blo1[2] = {wl[1][1], wl[1][3]};
                // variant-outer: same-accumulator dependency distance = 4
                mma16816(acc[mt][0], ah[cur], bhe0);
                mma16816(acc[mt][1], ah[cur], bho0);
                mma16816(acc[mt][2], ah[cur], bhe1);
                mma16816(acc[mt][3], ah[cur], bho1);
                mma16816(acc[mt][0], ah[cur], ble0);
                mma16816(acc[mt][1], ah[cur], blo0);
                mma16816(acc[mt][2], ah[cur], ble1);
                mma16816(acc[mt][3], ah[cur], blo1);
                mma16816(acc[mt][0], al[cur], bhe0);
                mma16816(acc[mt][1], al[cur], bho0);
                mma16816(acc[mt][2], al[cur], bhe1);
                mma16816(acc[mt][3], al[cur], bho1);
            }
        }
        __syncthreads();
    }

#pragma unroll
    for (int mt = 0; mt < 4; ++mt)
#pragma unroll
        for (int nt = 0; nt < 4; ++nt) {
            int row = bm + m0 + mt * 16 + g;
            int col = bn + n0 + nt * 8 + 2 * t4;
            if (split_out) {
                uint32_t hh, ll;
                split2(acc[mt][nt][0], acc[mt][nt][1], hh, ll);
                *(uint32_t*)&Ch[(size_t)row * N + col] = hh;
                *(uint32_t*)&Cl[(size_t)row * N + col] = ll;
                split2(acc[mt][nt][2], acc[mt][nt][3], hh, ll);
                *(uint32_t*)&Ch[(size_t)(row + 8) * N + col] = hh;
                *(uint32_t*)&Cl[(size_t)(row + 8) * N + col] = ll;
            } else {
                *(float2*)(Cf + (size_t)row * N + col) =
                    make_float2(acc[mt][nt][0], acc[mt][nt][1]);
                *(float2*)(Cf + (size_t)(row + 8) * N + col) =
                    make_float2(acc[mt][nt][2], acc[mt][nt][3]);
            }
        }
}

// ---------------- attention: 128-query tile, 8 warps, Q frags in registers --
#define TS 72
#define A_QH 0
#define A_QL (128*TS)
#define A_KV (2*128*TS)
#define A_KVSZ (4*64*TS)

__global__ __launch_bounds__(256) void attn_tc(
    const __nv_bfloat16* __restrict__ QKVh, const __nv_bfloat16* __restrict__ QKVl,
    const uint32_t* __restrict__ mbits,
    __nv_bfloat16* __restrict__ Oh, __nv_bfloat16* __restrict__ Ol)
{
    extern __shared__ __align__(16) __nv_bfloat16 sm[];

    const int b = blockIdx.z, h = blockIdx.y, s0 = blockIdx.x * 128;
    const int tid = threadIdx.x, lane = tid & 31, w = tid >> 5;
    const int g = lane >> 2, t4 = lane & 3;
    const int m0 = w * 16, l15 = lane & 15;

    // group 0: Q (own cp.async group)
    const __nv_bfloat16* qhp = QKVh + (size_t)(b * SS + s0) * NQKV + h * 64;
    const __nv_bfloat16* qlp = QKVl + (size_t)(b * SS + s0) * NQKV + h * 64;
#pragma unroll
    for (int it = 0; it < 8; ++it) {
        int c = it * 256 + tid;
        int r = (c & 1023) >> 3, u = c & 7;
        if (c < 1024) cp16(&sm[A_QH + r * TS + u * 8], qhp + (size_t)r * NQKV + u * 8);
        else          cp16(&sm[A_QL + r * TS + u * 8], qlp + (size_t)r * NQKV + u * 8);
    }
    CP_COMMIT();   // group g0 = Q

    const __nv_bfloat16* khp = QKVh + (size_t)(b * SS) * NQKV + DD + h * 64;
    const __nv_bfloat16* klp = QKVl + (size_t)(b * SS) * NQKV + DD + h * 64;
    const __nv_bfloat16* vhp = QKVh + (size_t)(b * SS) * NQKV + 2 * DD + h * 64;
    const __nv_bfloat16* vlp = QKVl + (size_t)(b * SS) * NQKV + 2 * DD + h * 64;

    auto stageKV = [&](int buf, int t0) {
        __nv_bfloat16* st = sm + A_KV + buf * A_KVSZ;
#pragma unroll
        for (int it = 0; it < 8; ++it) {
            int c = it * 256 + tid;
            int mat = c >> 9, r = (c >> 3) & 63, u = c & 7;
            const __nv_bfloat16* src =
                (mat == 0 ? khp : mat == 1 ? klp : mat == 2 ? vhp : vlp)
                + (size_t)(t0 + r) * NQKV + u * 8;
            cp16(st + mat * (64 * TS) + r * TS + u * 8, src);
        }
    };

    stageKV(0, 0);
    CP_COMMIT();   // group g1 = KV0

    CP_WAIT(1);    // Q (g0) complete
    __syncthreads();

    // hoist Q fragments into registers (reused for all 32 key tiles)
    uint32_t qfh[4][4], qfl[4][4];
#pragma unroll
    for (int ks4 = 0; ks4 < 4; ++ks4) {
        const int qo = (m0 + l15) * TS + ks4 * 16 + (lane >> 4) * 8;
        ldsm_x4(qfh[ks4], &sm[A_QH + qo]);
        ldsm_x4(qfl[ks4], &sm[A_QL + qo]);
    }

    float m_i[2] = {-1e30f, -1e30f}, l_i[2] = {0.f, 0.f};
    float oacc[8][4];
#pragma unroll
    for (int nt = 0; nt < 8; ++nt)
#pragma unroll
        for (int c = 0; c < 4; ++c) oacc[nt][c] = 0.f;

    const uint32_t* mb0 = mbits + ((size_t)b * SS + s0 + m0 + g) * (SS / 32);
    const uint32_t* mb8 = mb0 + 8 * (SS / 32);

    for (int i = 0; i < SS / 64; ++i) {
        const int t0 = i * 64, buf = i & 1;
        __syncthreads();
        if (i + 1 < SS / 64) { stageKV(buf ^ 1, t0 + 64); CP_COMMIT(); CP_WAIT(1); }
        else CP_WAIT(0);
        __syncthreads();

        const __nv_bfloat16* bKh = sm + A_KV + buf * A_KVSZ;
        const __nv_bfloat16* bKl = bKh + 64 * TS;
        const __nv_bfloat16* bVh = bKl + 64 * TS;
        const __nv_bfloat16* bVl = bVh + 64 * TS;

        float sc[8][4];
#pragma unroll
        for (int nt = 0; nt < 8; ++nt)
#pragma unroll
            for (int c = 0; c < 4; ++c) sc[nt][c] = 0.f;

#pragma unroll
        for (int ks4 = 0; ks4 < 4; ++ks4) {
            const int ks = ks4 * 16;
            uint32_t kh4[2][4], kl4[2][4];
            {
                const int ro = (l15) * TS + ks + (lane >> 4) * 8;
                ldsm_x4(kh4[0], bKh + ro);
                ldsm_x4(kl4[0], bKl + ro);
            }
#pragma unroll
            for (int nt2 = 0; nt2 < 4; ++nt2) {
                const int cur = nt2 & 1;
                if (nt2 < 3) {
                    const int ro = ((nt2 + 1) * 16 + l15) * TS + ks + (lane >> 4) * 8;
                    ldsm_x4(kh4[cur ^ 1], bKh + ro);
                    ldsm_x4(kl4[cur ^ 1], bKl + ro);
                }
                uint32_t bhe[2] = {kh4[cur][0], kh4[cur][2]}, bho[2] = {kh4[cur][1], kh4[cur][3]};
                uint32_t ble[2] = {kl4[cur][0], kl4[cur][2]}, blo[2] = {kl4[cur][1], kl4[cur][3]};
                mma16816(sc[2*nt2],   qfh[ks4], bhe);
                mma16816(sc[2*nt2+1], qfh[ks4], bho);
                mma16816(sc[2*nt2],   qfh[ks4], ble);
                mma16816(sc[2*nt2+1], qfh[ks4], blo);
                mma16816(sc[2*nt2],   qfl[ks4], bhe);
                mma16816(sc[2*nt2+1], qfl[ks4], bho);
            }
        }

        uint32_t wa0 = mb0[t0 >> 5], wb0 = mb0[(t0 >> 5) + 1];
        uint32_t wa8 = mb8[t0 >> 5], wb8 = mb8[(t0 >> 5) + 1];
        if ((wa0 & wb0 & wa8 & wb8) != 0xffffffffu) {
#pragma unroll
            for (int nt = 0; nt < 8; ++nt) {
                int c = nt * 8 + 2 * t4;
                uint32_t s0w = (c & 32) ? wb0 : wa0;
                uint32_t s8w = (c & 32) ? wb8 : wa8;
                int sh = c & 31;
                if (!((s0w >> sh) & 1))       sc[nt][0] = -1e10f;
                if (!((s0w >> (sh + 1)) & 1)) sc[nt][1] = -1e10f;
                if (!((s8w >> sh) & 1))       sc[nt][2] = -1e10f;
                if (!((s8w >> (sh + 1)) & 1)) sc[nt][3] = -1e10f;
            }
        }

        float mx0 = -1e30f, mx1 = -1e30f;
#pragma unroll
        for (int nt = 0; nt < 8; ++nt) {
            mx0 = fmaxf(mx0, fmaxf(sc[nt][0], sc[nt][1]));
            mx1 = fmaxf(mx1, fmaxf(sc[nt][2], sc[nt][3]));
        }
        mx0 = fmaxf(mx0, __shfl_xor_sync(0xffffffffu, mx0, 1));
        mx0 = fmaxf(mx0, __shfl_xor_sync(0xffffffffu, mx0, 2));
        mx1 = fmaxf(mx1, __shfl_xor_sync(0xffffffffu, mx1, 1));
        mx1 = fmaxf(mx1, __shfl_xor_sync(0xffffffffu, mx1, 2));

        float mn0 = fmaxf(m_i[0], mx0), mn1 = fmaxf(m_i[1], mx1);
        float corr0 = exp2f(m_i[0] - mn0), corr1 = exp2f(m_i[1] - mn1);
        m_i[0] = mn0; m_i[1] = mn1;

        float sum0 = 0.f, sum1 = 0.f;
#pragma unroll
        for (int nt = 0; nt < 8; ++nt) {
            sc[nt][0] = exp2f(sc[nt][0] - mn0);
            sc[nt][1] = exp2f(sc[nt][1] - mn0);
            sc[nt][2] = exp2f(sc[nt][2] - mn1);
            sc[nt][3] = exp2f(sc[nt][3] - mn1);
            sum0 += sc[nt][0] + sc[nt][1];
            sum1 += sc[nt][2] + sc[nt][3];
        }
        sum0 += __shfl_xor_sync(0xffffffffu, sum0, 1);
        sum0 += __shfl_xor_sync(0xffffffffu, sum0, 2);
        sum1 += __shfl_xor_sync(0xffffffffu, sum1, 1);
        sum1 += __shfl_xor_sync(0xffffffffu, sum1, 2);
        l_i[0] = l_i[0] * corr0 + sum0;
        l_i[1] = l_i[1] * corr1 + sum1;
#pragma unroll
        for (int nt = 0; nt < 8; ++nt) {
            oacc[nt][0] *= corr0; oacc[nt][1] *= corr0;
            oacc[nt][2] *= corr1; oacc[nt][3] *= corr1;
        }

#pragma unroll
        for (int j = 0; j < 4; ++j) {
            uint32_t ph[4], pl[4];
            split2(sc[2*j][0],   sc[2*j][1],   ph[0], pl[0]);
            split2(sc[2*j][2],   sc[2*j][3],   ph[1], pl[1]);
            split2(sc[2*j+1][0], sc[2*j+1][1], ph[2], pl[2]);
            split2(sc[2*j+1][2], sc[2*j+1][3], ph[3], pl[3]);

            uint32_t vh4[2][4], vl4[2][4];
            {
                const int ro = (j * 16 + l15) * TS + (lane >> 4) * 8;
                ldsm_x4t(vh4[0], bVh + ro);
                ldsm_x4t(vl4[0], bVl + ro);
            }
#pragma unroll
            for (int nt2 = 0; nt2 < 4; ++nt2) {
                const int cur = nt2 & 1;
                if (nt2 < 3) {
                    const int ro = (j * 16 + l15) * TS + (nt2 + 1) * 16 + (lane >> 4) * 8;
                    ldsm_x4t(vh4[cur ^ 1], bVh + ro);
                    ldsm_x4t(vl4[cur ^ 1], bVl + ro);
                }
                uint32_t vhe[2] = {vh4[cur][0], vh4[cur][1]}, vho[2] = {vh4[cur][2], vh4[cur][3]};
                uint32_t vle[2] = {vl4[cur][0], vl4[cur][1]}, vlo[2] = {vl4[cur][2], vl4[cur][3]};
                mma16816(oacc[2*nt2],   ph, vhe);
                mma16816(oacc[2*nt2+1], ph, vho);
                mma16816(oacc[2*nt2],   ph, vle);
                mma16816(oacc[2*nt2+1], ph, vlo);
                mma16816(oacc[2*nt2],   pl, vhe);
                mma16816(oacc[2*nt2+1], pl, vho);
            }
        }
    }

    float inv0 = __fdividef(1.f, l_i[0]);
    float inv1 = __fdividef(1.f, l_i[1]);
    size_t r0 = (size_t)(b * SS + s0 + m0 + g) * DD + h * 64;
    size_t r8 = r0 + (size_t)8 * DD;
#pragma unroll
    for (int nt = 0; nt < 8; ++nt) {
        int col = nt * 8 + 2 * t4;
        uint32_t hh, ll;
        split2(oacc[nt][0] * inv0, oacc[nt][1] * inv0, hh, ll);
        *(uint32_t*)&Oh[r0 + col] = hh; *(uint32_t*)&Ol[r0 + col] = ll;
        split2(oacc[nt][2] * inv1, oacc[nt][3] * inv1, hh, ll);
        *(uint32_t*)&Oh[r8 + col] = hh; *(uint32_t*)&Ol[r8 + col] = ll;
    }
}

// ---------------------------------------------------------------------------
extern "C" void kernel_launch(void* const* d_in, const int* in_sizes, int n_in,
                              void* d_out, int out_size)
{
    const float* queries = (const float*)d_in[0];
    const float* keys    = (const float*)d_in[1];
    const float* values  = (const float*)d_in[2];
    const int*   mask    = (const int*)  d_in[3];
    const float* Wq = (const float*)d_in[4];
    const float* Wk = (const float*)d_in[5];
    const float* Wv = (const float*)d_in[6];
    const float* Wo = (const float*)d_in[7];
    float* out = (float*)d_out;

    __nv_bfloat16 *xqh,*xql,*xkh,*xkl,*xvh,*xvl, *wqkvh,*wqkvl,*woh,*wol;
    __nv_bfloat16 *qkvh,*qkvl,*oh,*ol;
    uint32_t* mb;
    cudaGetSymbolAddress((void**)&xqh, g_xqh);   cudaGetSymbolAddress((void**)&xql, g_xql);
    cudaGetSymbolAddress((void**)&xkh, g_xkh);   cudaGetSymbolAddress((void**)&xkl, g_xkl);
    cudaGetSymbolAddress((void**)&xvh, g_xvh);   cudaGetSymbolAddress((void**)&xvl, g_xvl);
    cudaGetSymbolAddress((void**)&wqkvh, g_wqkvh); cudaGetSymbolAddress((void**)&wqkvl, g_wqkvl);
    cudaGetSymbolAddress((void**)&woh, g_woh);   cudaGetSymbolAddress((void**)&wol, g_wol);
    cudaGetSymbolAddress((void**)&qkvh, g_qkvh); cudaGetSymbolAddress((void**)&qkvl, g_qkvl);
    cudaGetSymbolAddress((void**)&oh, g_oh);     cudaGetSymbolAddress((void**)&ol, g_ol);
    cudaGetSymbolAddress((void**)&mb, g_mbits);

    const int GEMM_SMEM = 2 * GSTAGE * (int)sizeof(__nv_bfloat16);                  // 81920
    cudaFuncSetAttribute(gemm_mma, cudaFuncAttributeMaxDynamicSharedMemorySize, GEMM_SMEM);
    const int ATTN_SMEM = (2 * 128 * TS + 2 * A_KVSZ) * (int)sizeof(__nv_bfloat16); // 110592
    cudaFuncSetAttribute(attn_tc, cudaFuncAttributeMaxDynamicSharedMemorySize, ATTN_SMEM);

    const int n4i = MTOK * DD / 4, n4w = DD * DD / 4;
    split3_kernel<<<dim3(n4i / 1024, 3), 256>>>(
        (const float4*)queries, (const float4*)keys, (const float4*)values,
        (uint2*)xqh, (uint2*)xql, (uint2*)xkh, (uint2*)xkl, (uint2*)xvh, (uint2*)xvl, n4i);
    splitw_kernel<<<dim3(n4w / 256, 4), 256>>>(
        (const float4*)Wq, (const float4*)Wk, (const float4*)Wv, (const float4*)Wo,
        (uint2*)wqkvh, (uint2*)wqkvl, (uint2*)woh, (uint2*)wol, n4w);
    maskbits_kernel<<<(int)((size_t)BB * SS * SS / 128 / 8), 256>>>(mask, mb);

    gemm_mma<<<dim3(NQKV / 128, MTOK / 128), 256, GEMM_SMEM>>>(
        xqh, xql, xkh, xkl, xvh, xvl, wqkvh, wqkvl,
        nullptr, qkvh, qkvl, NQKV, DD, 1);

    attn_tc<<<dim3(SS / 128, HH, BB), 256, ATTN_SMEM>>>(qkvh, qkvl, mb, oh, ol);

    gemm_mma<<<dim3(DD / 128, MTOK / 128), 256, GEMM_SMEM>>>(
        oh, ol, oh, ol, oh, ol, woh, wol,
        out, nullptr, nullptr, DD, DD, 0);
}

// round 13
// speedup vs baseline: 1.0015x; 1.0015x over previous
#include <cuda_runtime.h>
#include <cuda_bf16.h>
#include <cstdint>
#include <cstddef>

#define BB 4
#define SS 2048
#define DD 1024
#define HH 16
#define MTOK (BB*SS)
#define NQKV (3*DD)
#define QSCALE 0.1803368801111204f   // 0.125 * log2(e)

// ---------------- scratch (__device__ globals; allocs forbidden) ----------
__device__ __nv_bfloat16 g_xqh[MTOK*DD], g_xql[MTOK*DD];
__device__ __nv_bfloat16 g_xkh[MTOK*DD], g_xkl[MTOK*DD];
__device__ __nv_bfloat16 g_xvh[MTOK*DD], g_xvl[MTOK*DD];
__device__ __nv_bfloat16 g_wqkvh[3*DD*DD], g_wqkvl[3*DD*DD];
__device__ __nv_bfloat16 g_woh[DD*DD], g_wol[DD*DD];
__device__ __nv_bfloat16 g_qkvh[(size_t)MTOK*NQKV], g_qkvl[(size_t)MTOK*NQKV];
__device__ __nv_bfloat16 g_oh[MTOK*DD], g_ol[MTOK*DD];
__device__ uint32_t g_mbits[(size_t)BB*SS*(SS/32)];

// ---------------- helpers --------------------------------------------------
__device__ __forceinline__ uint32_t smem_u32(const void* p) {
    return (uint32_t)__cvta_generic_to_shared(p);
}
__device__ __forceinline__ void mma16816(float* c, const uint32_t* a, const uint32_t* b) {
    asm volatile(
        "mma.sync.aligned.m16n8k16.row.col.f32.bf16.bf16.f32 "
        "{%0,%1,%2,%3},{%4,%5,%6,%7},{%8,%9},{%0,%1,%2,%3};"
        : "+f"(c[0]), "+f"(c[1]), "+f"(c[2]), "+f"(c[3])
        : "r"(a[0]), "r"(a[1]), "r"(a[2]), "r"(a[3]), "r"(b[0]), "r"(b[1]));
}
__device__ __forceinline__ void ldsm_x4(uint32_t* r, const void* p) {
    uint32_t a = smem_u32(p);
    asm volatile("ldmatrix.sync.aligned.m8n8.x4.shared.b16 {%0,%1,%2,%3},[%4];"
                 : "=r"(r[0]), "=r"(r[1]), "=r"(r[2]), "=r"(r[3]) : "r"(a));
}
__device__ __forceinline__ void ldsm_x4t(uint32_t* r, const void* p) {
    uint32_t a = smem_u32(p);
    asm volatile("ldmatrix.sync.aligned.m8n8.x4.trans.shared.b16 {%0,%1,%2,%3},[%4];"
                 : "=r"(r[0]), "=r"(r[1]), "=r"(r[2]), "=r"(r[3]) : "r"(a));
}
__device__ __forceinline__ void split2(float f0, float f1, uint32_t& hi, uint32_t& lo) {
    __nv_bfloat162 h = __floats2bfloat162_rn(f0, f1);
    float r0 = f0 - __bfloat162float(h.x);
    float r1 = f1 - __bfloat162float(h.y);
    hi = *reinterpret_cast<uint32_t*>(&h);
    __nv_bfloat162 l = __floats2bfloat162_rn(r0, r1);
    lo = *reinterpret_cast<uint32_t*>(&l);
}
__device__ __forceinline__ void cp16(void* s, const void* g) {
    uint32_t sa = smem_u32(s);
    asm volatile("cp.async.cg.shared.global [%0], [%1], 16;" :: "r"(sa), "l"(g));
}
#define CP_COMMIT() asm volatile("cp.async.commit_group;" ::: "memory")
#define CP_WAIT(n)  asm volatile("cp.async.wait_group %0;" :: "n"(n) : "memory")

// ---------------- prepass kernels ------------------------------------------
__global__ void split3_kernel(const float4* __restrict__ x0, const float4* __restrict__ x1,
                              const float4* __restrict__ x2,
                              uint2* __restrict__ h0, uint2* __restrict__ l0,
                              uint2* __restrict__ h1, uint2* __restrict__ l1,
                              uint2* __restrict__ h2, uint2* __restrict__ l2, int n4) {
    int base = blockIdx.x * 1024 + threadIdx.x;
    const float4* x = (blockIdx.y == 0) ? x0 : (blockIdx.y == 1) ? x1 : x2;
    uint2* h = (blockIdx.y == 0) ? h0 : (blockIdx.y == 1) ? h1 : h2;
    uint2* l = (blockIdx.y == 0) ? l0 : (blockIdx.y == 1) ? l1 : l2;
    float4 v[4];
#pragma unroll
    for (int r = 0; r < 4; ++r) v[r] = x[base + r * 256];
#pragma unroll
    for (int r = 0; r < 4; ++r) {
        uint2 hh, ll;
        split2(v[r].x, v[r].y, hh.x, ll.x);
        split2(v[r].z, v[r].w, hh.y, ll.y);
        h[base + r * 256] = hh;
        l[base + r * 256] = ll;
    }
}
__global__ void splitw_kernel(const float4* __restrict__ wq, const float4* __restrict__ wk,
                              const float4* __restrict__ wv, const float4* __restrict__ wo,
                              uint2* __restrict__ qkvh, uint2* __restrict__ qkvl,
                              uint2* __restrict__ woh, uint2* __restrict__ wol, int n4) {
    int i = blockIdx.x * 256 + threadIdx.x;
    if (i >= n4) return;
    int y = blockIdx.y;
    const float4* src = (y == 0) ? wq : (y == 1) ? wk : (y == 2) ? wv : wo;
    float4 v = src[i];
    if (y == 0) { v.x *= QSCALE; v.y *= QSCALE; v.z *= QSCALE; v.w *= QSCALE; }
    uint2 hh, ll;
    split2(v.x, v.y, hh.x, ll.x);
    split2(v.z, v.w, hh.y, ll.y);
    uint2* h = (y < 3) ? (qkvh + (size_t)y * n4) : woh;
    uint2* l = (y < 3) ? (qkvl + (size_t)y * n4) : wol;
    h[i] = hh; l[i] = ll;
}
__global__ void maskbits_kernel(const int* __restrict__ m, uint32_t* __restrict__ bits) {
    size_t w = (size_t)blockIdx.x * 8 + (threadIdx.x >> 5);
    int lane = threadIdx.x & 31;
    const int* p = m + w * 128;
    int v0 = p[lane], v1 = p[lane + 32], v2 = p[lane + 64], v3 = p[lane + 96];
    uint32_t b0 = __ballot_sync(0xffffffffu, v0 != 0);
    uint32_t b1 = __ballot_sync(0xffffffffu, v1 != 0);
    uint32_t b2 = __ballot_sync(0xffffffffu, v2 != 0);
    uint32_t b3 = __ballot_sync(0xffffffffu, v3 != 0);
    if (lane == 0) { bits[w*4] = b0; bits[w*4+1] = b1; bits[w*4+2] = b2; bits[w*4+3] = b3; }
}

// ---------------- GEMM: 128x128 tile, 2 CTAs/SM, 2-stage (R10 proven) -------
#define GST 40
#define G_AH 0
#define G_AL (128*GST)
#define G_WH (2*128*GST)
#define G_WL (3*128*GST)
#define GSTAGE (4*128*GST)

__global__ __launch_bounds__(256, 2) void gemm_mma(
    const __nv_bfloat16* __restrict__ A0h, const __nv_bfloat16* __restrict__ A0l,
    const __nv_bfloat16* __restrict__ A1h, const __nv_bfloat16* __restrict__ A1l,
    const __nv_bfloat16* __restrict__ A2h, const __nv_bfloat16* __restrict__ A2l,
    const __nv_bfloat16* __restrict__ Wh, const __nv_bfloat16* __restrict__ Wl,
    float* __restrict__ Cf, __nv_bfloat16* __restrict__ Ch, __nv_bfloat16* __restrict__ Cl,
    int N, int K, int split_out)
{
    extern __shared__ __align__(16) __nv_bfloat16 sg[];

    const int tid = threadIdx.x, lane = tid & 31, w = tid >> 5;
    const int g = lane >> 2, t4 = lane & 3, l15 = lane & 15;
    const int m0 = (w >> 2) * 64, n0 = (w & 3) * 32;
    const int bm = blockIdx.y * 128, bn = blockIdx.x * 128;

    const int sel = bn >> 10;
    const __nv_bfloat16* Ah = (sel == 0) ? A0h : (sel == 1) ? A1h : A2h;
    const __nv_bfloat16* Al = (sel == 0) ? A0l : (sel == 1) ? A1l : A2l;

    const __nv_bfloat16* pAh = Ah + (size_t)bm * K;
    const __nv_bfloat16* pAl = Al + (size_t)bm * K;
    const __nv_bfloat16* pWh = Wh + (size_t)bn * K;
    const __nv_bfloat16* pWl = Wl + (size_t)bn * K;

    auto stage = [&](int buf, int k0) {
        __nv_bfloat16* st = sg + buf * GSTAGE;
#pragma unroll
        for (int it = 0; it < 8; ++it) {
            int c = it * 256 + tid;
            int mat = c >> 9, r = (c >> 2) & 127, u = c & 3;
            const __nv_bfloat16* src =
                (mat == 0 ? pAh : mat == 1 ? pAl : mat == 2 ? pWh : pWl)
                + (size_t)r * K + k0 + u * 8;
            cp16(st + mat * (128 * GST) + r * GST + u * 8, src);
        }
    };

    float acc[4][4][4];
#pragma unroll
    for (int i = 0; i < 4; ++i)
#pragma unroll
        for (int j = 0; j < 4; ++j)
#pragma unroll
            for (int c = 0; c < 4; ++c) acc[i][j][c] = 0.f;

    const int NST = K / 32;
    stage(0, 0); CP_COMMIT();

    for (int kt = 0; kt < NST; ++kt) {
        const int buf = kt & 1;
        if (kt + 1 < NST) { stage(buf ^ 1, (kt + 1) * 32); CP_COMMIT(); CP_WAIT(1); }
        else CP_WAIT(0);
        __syncthreads();

        const __nv_bfloat16* st = sg + buf * GSTAGE;
#pragma unroll
        for (int ks = 0; ks < 32; ks += 16) {
            uint32_t wh[2][4], wl[2][4];
            {
                const int ro0 = (n0 + l15) * GST + ks + (lane >> 4) * 8;
                const int ro1 = (n0 + 16 + l15) * GST + ks + (lane >> 4) * 8;
                ldsm_x4(wh[0], st + G_WH + ro0);
                ldsm_x4(wl[0], st + G_WL + ro0);
                ldsm_x4(wh[1], st + G_WH + ro1);
                ldsm_x4(wl[1], st + G_WL + ro1);
            }
            uint32_t ah[2][4], al[2][4];
            {
                const int ro = (m0 + l15) * GST + ks + (lane >> 4) * 8;
                ldsm_x4(ah[0], st + G_AH + ro);
                ldsm_x4(al[0], st + G_AL + ro);
            }
#pragma unroll
            for (int mt = 0; mt < 4; ++mt) {
                const int cur = mt & 1;
                if (mt < 3) {
                    const int ro = (m0 + (mt + 1) * 16 + l15) * GST + ks + (lane >> 4) * 8;
                    ldsm_x4(ah[cur ^ 1], st + G_AH + ro);
                    ldsm_x4(al[cur ^ 1], st + G_AL + ro);
                }
#pragma unroll
                for (int nn = 0; nn < 2; ++nn) {
                    uint32_t bhe[2] = {wh[nn][0], wh[nn][2]}, bho[2] = {wh[nn][1], wh[nn][3]};
                    uint32_t ble[2] = {wl[nn][0], wl[nn][2]}, blo[2] = {wl[nn][1], wl[nn][3]};
                    mma16816(acc[mt][2*nn],   ah[cur], bhe);
                    mma16816(acc[mt][2*nn+1], ah[cur], bho);
                    mma16816(acc[mt][2*nn],   ah[cur], ble);
                    mma16816(acc[mt][2*nn+1], ah[cur], blo);
                    mma16816(acc[mt][2*nn],   al[cur], bhe);
                    mma16816(acc[mt][2*nn+1], al[cur], bho);
                }
            }
        }
        __syncthreads();
    }

#pragma unroll
    for (int mt = 0; mt < 4; ++mt)
#pragma unroll
        for (int nt = 0; nt < 4; ++nt) {
            int row = bm + m0 + mt * 16 + g;
            int col = bn + n0 + nt * 8 + 2 * t4;
            if (split_out) {
                uint32_t hh, ll;
                split2(acc[mt][nt][0], acc[mt][nt][1], hh, ll);
                *(uint32_t*)&Ch[(size_t)row * N + col] = hh;
                *(uint32_t*)&Cl[(size_t)row * N + col] = ll;
                split2(acc[mt][nt][2], acc[mt][nt][3], hh, ll);
                *(uint32_t*)&Ch[(size_t)(row + 8) * N + col] = hh;
                *(uint32_t*)&Cl[(size_t)(row + 8) * N + col] = ll;
            } else {
                *(float2*)(Cf + (size_t)row * N + col) =
                    make_float2(acc[mt][nt][0], acc[mt][nt][1]);
                *(float2*)(Cf + (size_t)(row + 8) * N + col) =
                    make_float2(acc[mt][nt][2], acc[mt][nt][3]);
            }
        }
}

// ---------------- attention: 64-query / 128-thread CTA, 2 CTAs per SM -------
#define TS 72
#define A_QH 0
#define A_QL (64*TS)
#define A_KV (2*64*TS)
#define A_KVSZ (4*64*TS)
#define ATTN_SMEM_BYTES ((2*64*TS + 2*A_KVSZ) * (int)sizeof(__nv_bfloat16))  // 92160

__global__ __launch_bounds__(128) void attn_tc(
    const __nv_bfloat16* __restrict__ QKVh, const __nv_bfloat16* __restrict__ QKVl,
    const uint32_t* __restrict__ mbits,
    __nv_bfloat16* __restrict__ Oh, __nv_bfloat16* __restrict__ Ol)
{
    extern __shared__ __align__(16) __nv_bfloat16 sm[];

    const int b = blockIdx.z, h = blockIdx.y, s0 = blockIdx.x * 64;
    const int tid = threadIdx.x, lane = tid & 31, w = tid >> 5;
    const int g = lane >> 2, t4 = lane & 3;
    const int m0 = w * 16, l15 = lane & 15;

    // stage Q (64 rows x 64, hi+lo); pre-scaled via Wq
    const __nv_bfloat16* qhp = QKVh + (size_t)(b * SS + s0) * NQKV + h * 64;
    const __nv_bfloat16* qlp = QKVl + (size_t)(b * SS + s0) * NQKV + h * 64;
#pragma unroll
    for (int it = 0; it < 8; ++it) {
        int c = it * 128 + tid;            // 0..1023
        if (c < 512) {
            int r = c >> 3, u = c & 7;
            cp16(&sm[A_QH + r * TS + u * 8], qhp + (size_t)r * NQKV + u * 8);
        } else {
            int cc = c - 512, r = cc >> 3, u = cc & 7;
            cp16(&sm[A_QL + r * TS + u * 8], qlp + (size_t)r * NQKV + u * 8);
        }
    }

    const __nv_bfloat16* khp = QKVh + (size_t)(b * SS) * NQKV + DD + h * 64;
    const __nv_bfloat16* klp = QKVl + (size_t)(b * SS) * NQKV + DD + h * 64;
    const __nv_bfloat16* vhp = QKVh + (size_t)(b * SS) * NQKV + 2 * DD + h * 64;
    const __nv_bfloat16* vlp = QKVl + (size_t)(b * SS) * NQKV + 2 * DD + h * 64;

    auto stageKV = [&](int buf, int t0) {
        __nv_bfloat16* st = sm + A_KV + buf * A_KVSZ;
#pragma unroll
        for (int it = 0; it < 16; ++it) {
            int c = it * 128 + tid;        // 0..2047
            int mat = c >> 9, r = (c >> 3) & 63, u = c & 7;
            const __nv_bfloat16* src =
                (mat == 0 ? khp : mat == 1 ? klp : mat == 2 ? vhp : vlp)
                + (size_t)(t0 + r) * NQKV + u * 8;
            cp16(st + mat * (64 * TS) + r * TS + u * 8, src);
        }
    };

    stageKV(0, 0);
    CP_COMMIT();

    float m_i[2] = {-1e30f, -1e30f}, l_i[2] = {0.f, 0.f};
    float oacc[8][4];
#pragma unroll
    for (int nt = 0; nt < 8; ++nt)
#pragma unroll
        for (int c = 0; c < 4; ++c) oacc[nt][c] = 0.f;

    const uint32_t* mb0 = mbits + ((size_t)b * SS + s0 + m0 + g) * (SS / 32);
    const uint32_t* mb8 = mb0 + 8 * (SS / 32);

    for (int i = 0; i < SS / 64; ++i) {
        const int t0 = i * 64, buf = i & 1;
        __syncthreads();
        if (i + 1 < SS / 64) { stageKV(buf ^ 1, t0 + 64); CP_COMMIT(); CP_WAIT(1); }
        else CP_WAIT(0);
        __syncthreads();

        const __nv_bfloat16* bKh = sm + A_KV + buf * A_KVSZ;
        const __nv_bfloat16* bKl = bKh + 64 * TS;
        const __nv_bfloat16* bVh = bKl + 64 * TS;
        const __nv_bfloat16* bVl = bVh + 64 * TS;

        // ---- S = Q K^T ----
        float sc[8][4];
#pragma unroll
        for (int nt = 0; nt < 8; ++nt)
#pragma unroll
            for (int c = 0; c < 4; ++c) sc[nt][c] = 0.f;

#pragma unroll
        for (int ks = 0; ks < 64; ks += 16) {
            uint32_t qfh[4], qfl[4];
            const int qo = (m0 + l15) * TS + ks + (lane >> 4) * 8;
            ldsm_x4(qfh, &sm[A_QH + qo]);
            ldsm_x4(qfl, &sm[A_QL + qo]);

            uint32_t kh4[2][4], kl4[2][4];
            {
                const int ro = (l15) * TS + ks + (lane >> 4) * 8;
                ldsm_x4(kh4[0], bKh + ro);
                ldsm_x4(kl4[0], bKl + ro);
            }
#pragma unroll
            for (int nt2 = 0; nt2 < 4; ++nt2) {
                const int cur = nt2 & 1;
                if (nt2 < 3) {
                    const int ro = ((nt2 + 1) * 16 + l15) * TS + ks + (lane >> 4) * 8;
                    ldsm_x4(kh4[cur ^ 1], bKh + ro);
                    ldsm_x4(kl4[cur ^ 1], bKl + ro);
                }
                uint32_t bhe[2] = {kh4[cur][0], kh4[cur][2]}, bho[2] = {kh4[cur][1], kh4[cur][3]};
                uint32_t ble[2] = {kl4[cur][0], kl4[cur][2]}, blo[2] = {kl4[cur][1], kl4[cur][3]};
                mma16816(sc[2*nt2],   qfh, bhe);
                mma16816(sc[2*nt2+1], qfh, bho);
                mma16816(sc[2*nt2],   qfh, ble);
                mma16816(sc[2*nt2+1], qfh, blo);
                mma16816(sc[2*nt2],   qfl, bhe);
                mma16816(sc[2*nt2+1], qfl, bho);
            }
        }

        // ---- mask (all-ones fast path; Q pre-scaled) ----
        uint32_t wa0 = mb0[t0 >> 5], wb0 = mb0[(t0 >> 5) + 1];
        uint32_t wa8 = mb8[t0 >> 5], wb8 = mb8[(t0 >> 5) + 1];
        if ((wa0 & wb0 & wa8 & wb8) != 0xffffffffu) {
#pragma unroll
            for (int nt = 0; nt < 8; ++nt) {
                int c = nt * 8 + 2 * t4;
                uint32_t s0w = (c & 32) ? wb0 : wa0;
                uint32_t s8w = (c & 32) ? wb8 : wa8;
                int sh = c & 31;
                if (!((s0w >> sh) & 1))       sc[nt][0] = -1e10f;
                if (!((s0w >> (sh + 1)) & 1)) sc[nt][1] = -1e10f;
                if (!((s8w >> sh) & 1))       sc[nt][2] = -1e10f;
                if (!((s8w >> (sh + 1)) & 1)) sc[nt][3] = -1e10f;
            }
        }

        // ---- online softmax (base 2) ----
        float mx0 = -1e30f, mx1 = -1e30f;
#pragma unroll
        for (int nt = 0; nt < 8; ++nt) {
            mx0 = fmaxf(mx0, fmaxf(sc[nt][0], sc[nt][1]));
            mx1 = fmaxf(mx1, fmaxf(sc[nt][2], sc[nt][3]));
        }
        mx0 = fmaxf(mx0, __shfl_xor_sync(0xffffffffu, mx0, 1));
        mx0 = fmaxf(mx0, __shfl_xor_sync(0xffffffffu, mx0, 2));
        mx1 = fmaxf(mx1, __shfl_xor_sync(0xffffffffu, mx1, 1));
        mx1 = fmaxf(mx1, __shfl_xor_sync(0xffffffffu, mx1, 2));

        float mn0 = fmaxf(m_i[0], mx0), mn1 = fmaxf(m_i[1], mx1);
        float corr0 = exp2f(m_i[0] - mn0), corr1 = exp2f(m_i[1] - mn1);
        m_i[0] = mn0; m_i[1] = mn1;

        float sum0 = 0.f, sum1 = 0.f;
#pragma unroll
        for (int nt = 0; nt < 8; ++nt) {
            sc[nt][0] = exp2f(sc[nt][0] - mn0);
            sc[nt][1] = exp2f(sc[nt][1] - mn0);
            sc[nt][2] = exp2f(sc[nt][2] - mn1);
            sc[nt][3] = exp2f(sc[nt][3] - mn1);
            sum0 += sc[nt][0] + sc[nt][1];
            sum1 += sc[nt][2] + sc[nt][3];
        }
        sum0 += __shfl_xor_sync(0xffffffffu, sum0, 1);
        sum0 += __shfl_xor_sync(0xffffffffu, sum0, 2);
        sum1 += __shfl_xor_sync(0xffffffffu, sum1, 1);
        sum1 += __shfl_xor_sync(0xffffffffu, sum1, 2);
        l_i[0] = l_i[0] * corr0 + sum0;
        l_i[1] = l_i[1] * corr1 + sum1;
#pragma unroll
        for (int nt = 0; nt < 8; ++nt) {
            oacc[nt][0] *= corr0; oacc[nt][1] *= corr0;
            oacc[nt][2] *= corr1; oacc[nt][3] *= corr1;
        }

        // ---- O += P V (P in registers, V fragments pipelined) ----
#pragma unroll
        for (int j = 0; j < 4; ++j) {
            uint32_t ph[4], pl[4];
            split2(sc[2*j][0],   sc[2*j][1],   ph[0], pl[0]);
            split2(sc[2*j][2],   sc[2*j][3],   ph[1], pl[1]);
            split2(sc[2*j+1][0], sc[2*j+1][1], ph[2], pl[2]);
            split2(sc[2*j+1][2], sc[2*j+1][3], ph[3], pl[3]);

            uint32_t vh4[2][4], vl4[2][4];
            {
                const int ro = (j * 16 + l15) * TS + (lane >> 4) * 8;
                ldsm_x4t(vh4[0], bVh + ro);
                ldsm_x4t(vl4[0], bVl + ro);
            }
#pragma unroll
            for (int nt2 = 0; nt2 < 4; ++nt2) {
                const int cur = nt2 & 1;
                if (nt2 < 3) {
                    const int ro = (j * 16 + l15) * TS + (nt2 + 1) * 16 + (lane >> 4) * 8;
                    ldsm_x4t(vh4[cur ^ 1], bVh + ro);
                    ldsm_x4t(vl4[cur ^ 1], bVl + ro);
                }
                uint32_t vhe[2] = {vh4[cur][0], vh4[cur][1]}, vho[2] = {vh4[cur][2], vh4[cur][3]};
                uint32_t vle[2] = {vl4[cur][0], vl4[cur][1]}, vlo[2] = {vl4[cur][2], vl4[cur][3]};
                mma16816(oacc[2*nt2],   ph, vhe);
                mma16816(oacc[2*nt2+1], ph, vho);
                mma16816(oacc[2*nt2],   ph, vle);
                mma16816(oacc[2*nt2+1], ph, vlo);
                mma16816(oacc[2*nt2],   pl, vhe);
                mma16816(oacc[2*nt2+1], pl, vho);
            }
        }
    }

    // ---- epilogue ----
    float inv0 = __fdividef(1.f, l_i[0]);
    float inv1 = __fdividef(1.f, l_i[1]);
    size_t r0 = (size_t)(b * SS + s0 + m0 + g) * DD + h * 64;
    size_t r8 = r0 + (size_t)8 * DD;
#pragma unroll
    for (int nt = 0; nt < 8; ++nt) {
        int col = nt * 8 + 2 * t4;
        uint32_t hh, ll;
        split2(oacc[nt][0] * inv0, oacc[nt][1] * inv0, hh, ll);
        *(uint32_t*)&Oh[r0 + col] = hh; *(uint32_t*)&Ol[r0 + col] = ll;
        split2(oacc[nt][2] * inv1, oacc[nt][3] * inv1, hh, ll);
        *(uint32_t*)&Oh[r8 + col] = hh; *(uint32_t*)&Ol[r8 + col] = ll;
    }
}

// ---------------------------------------------------------------------------
extern "C" void kernel_launch(void* const* d_in, const int* in_sizes, int n_in,
                              void* d_out, int out_size)
{
    const float* queries = (const float*)d_in[0];
    const float* keys    = (const float*)d_in[1];
    const float* values  = (const float*)d_in[2];
    const int*   mask    = (const int*)  d_in[3];
    const float* Wq = (const float*)d_in[4];
    const float* Wk = (const float*)d_in[5];
    const float* Wv = (const float*)d_in[6];
    const float* Wo = (const float*)d_in[7];
    float* out = (float*)d_out;

    __nv_bfloat16 *xqh,*xql,*xkh,*xkl,*xvh,*xvl, *wqkvh,*wqkvl,*woh,*wol;
    __nv_bfloat16 *qkvh,*qkvl,*oh,*ol;
    uint32_t* mb;
    cudaGetSymbolAddress((void**)&xqh, g_xqh);   cudaGetSymbolAddress((void**)&xql, g_xql);
    cudaGetSymbolAddress((void**)&xkh, g_xkh);   cudaGetSymbolAddress((void**)&xkl, g_xkl);
    cudaGetSymbolAddress((void**)&xvh, g_xvh);   cudaGetSymbolAddress((void**)&xvl, g_xvl);
    cudaGetSymbolAddress((void**)&wqkvh, g_wqkvh); cudaGetSymbolAddress((void**)&wqkvl, g_wqkvl);
    cudaGetSymbolAddress((void**)&woh, g_woh);   cudaGetSymbolAddress((void**)&wol, g_wol);
    cudaGetSymbolAddress((void**)&qkvh, g_qkvh); cudaGetSymbolAddress((void**)&qkvl, g_qkvl);
    cudaGetSymbolAddress((void**)&oh, g_oh);     cudaGetSymbolAddress((void**)&ol, g_ol);
    cudaGetSymbolAddress((void**)&mb, g_mbits);

    const int GEMM_SMEM = 2 * GSTAGE * (int)sizeof(__nv_bfloat16);   // 81920
    cudaFuncSetAttribute(gemm_mma, cudaFuncAttributeMaxDynamicSharedMemorySize, GEMM_SMEM);
    cudaFuncSetAttribute(attn_tc, cudaFuncAttributeMaxDynamicSharedMemorySize, ATTN_SMEM_BYTES);

    const int n4i = MTOK * DD / 4, n4w = DD * DD / 4;
    split3_kernel<<<dim3(n4i / 1024, 3), 256>>>(
        (const float4*)queries, (const float4*)keys, (const float4*)values,
        (uint2*)xqh, (uint2*)xql, (uint2*)xkh, (uint2*)xkl, (uint2*)xvh, (uint2*)xvl, n4i);
    splitw_kernel<<<dim3(n4w / 256, 4), 256>>>(
        (const float4*)Wq, (const float4*)Wk, (const float4*)Wv, (const float4*)Wo,
        (uint2*)wqkvh, (uint2*)wqkvl, (uint2*)woh, (uint2*)wol, n4w);
    maskbits_kernel<<<(int)((size_t)BB * SS * SS / 128 / 8), 256>>>(mask, mb);

    gemm_mma<<<dim3(NQKV / 128, MTOK / 128), 256, GEMM_SMEM>>>(
        xqh, xql, xkh, xkl, xvh, xvl, wqkvh, wqkvl,
        nullptr, qkvh, qkvl, NQKV, DD, 1);

    attn_tc<<<dim3(SS / 64, HH, BB), 128, ATTN_SMEM_BYTES>>>(qkvh, qkvl, mb, oh, ol);

    gemm_mma<<<dim3(DD / 128, MTOK / 128), 256, GEMM_SMEM>>>(
        oh, ol, oh, ol, oh, ol, woh, wol,
        out, nullptr, nullptr, DD, DD, 0);
}

// round 14
// speedup vs baseline: 1.0676x; 1.0660x over previous
#include <cuda_runtime.h>
#include <cuda_bf16.h>
#include <cstdint>
#include <cstddef>

#define BB 4
#define SS 2048
#define DD 1024
#define HH 16
#define MTOK (BB*SS)
#define NQKV (3*DD)
#define QSCALE 0.1803368801111204f   // 0.125 * log2(e)

// ---------------- scratch (__device__ globals; allocs forbidden) ----------
__device__ __nv_bfloat16 g_xqh[MTOK*DD], g_xql[MTOK*DD];
__device__ __nv_bfloat16 g_xkh[MTOK*DD], g_xkl[MTOK*DD];
__device__ __nv_bfloat16 g_xvh[MTOK*DD], g_xvl[MTOK*DD];
__device__ __nv_bfloat16 g_wqkvh[3*DD*DD], g_wqkvl[3*DD*DD];
__device__ __nv_bfloat16 g_woh[DD*DD], g_wol[DD*DD];
__device__ __nv_bfloat16 g_qkvh[(size_t)MTOK*NQKV], g_qkvl[(size_t)MTOK*NQKV];
__device__ __nv_bfloat16 g_oh[MTOK*DD], g_ol[MTOK*DD];
__device__ uint32_t g_mbits[(size_t)BB*SS*(SS/32)];

// ---------------- helpers --------------------------------------------------
__device__ __forceinline__ uint32_t smem_u32(const void* p) {
    return (uint32_t)__cvta_generic_to_shared(p);
}
__device__ __forceinline__ void mma16816(float* c, const uint32_t* a, const uint32_t* b) {
    asm volatile(
        "mma.sync.aligned.m16n8k16.row.col.f32.bf16.bf16.f32 "
        "{%0,%1,%2,%3},{%4,%5,%6,%7},{%8,%9},{%0,%1,%2,%3};"
        : "+f"(c[0]), "+f"(c[1]), "+f"(c[2]), "+f"(c[3])
        : "r"(a[0]), "r"(a[1]), "r"(a[2]), "r"(a[3]), "r"(b[0]), "r"(b[1]));
}
__device__ __forceinline__ void ldsm_x4(uint32_t* r, const void* p) {
    uint32_t a = smem_u32(p);
    asm volatile("ldmatrix.sync.aligned.m8n8.x4.shared.b16 {%0,%1,%2,%3},[%4];"
                 : "=r"(r[0]), "=r"(r[1]), "=r"(r[2]), "=r"(r[3]) : "r"(a));
}
__device__ __forceinline__ void ldsm_x4t(uint32_t* r, const void* p) {
    uint32_t a = smem_u32(p);
    asm volatile("ldmatrix.sync.aligned.m8n8.x4.trans.shared.b16 {%0,%1,%2,%3},[%4];"
                 : "=r"(r[0]), "=r"(r[1]), "=r"(r[2]), "=r"(r[3]) : "r"(a));
}
__device__ __forceinline__ void split2(float f0, float f1, uint32_t& hi, uint32_t& lo) {
    __nv_bfloat162 h = __floats2bfloat162_rn(f0, f1);
    float r0 = f0 - __bfloat162float(h.x);
    float r1 = f1 - __bfloat162float(h.y);
    hi = *reinterpret_cast<uint32_t*>(&h);
    __nv_bfloat162 l = __floats2bfloat162_rn(r0, r1);
    lo = *reinterpret_cast<uint32_t*>(&l);
}
__device__ __forceinline__ void cp16(void* s, const void* g) {
    uint32_t sa = smem_u32(s);
    asm volatile("cp.async.cg.shared.global [%0], [%1], 16;" :: "r"(sa), "l"(g));
}
#define CP_COMMIT() asm volatile("cp.async.commit_group;" ::: "memory")
#define CP_WAIT(n)  asm volatile("cp.async.wait_group %0;" :: "n"(n) : "memory")

// ---------------- prepass kernels ------------------------------------------
// input split, MLP=4
__global__ void split3_kernel(const float4* __restrict__ x0, const float4* __restrict__ x1,
                              const float4* __restrict__ x2,
                              uint2* __restrict__ h0, uint2* __restrict__ l0,
                              uint2* __restrict__ h1, uint2* __restrict__ l1,
                              uint2* __restrict__ h2, uint2* __restrict__ l2, int n4) {
    int base = blockIdx.x * 1024 + threadIdx.x;
    const float4* x = (blockIdx.y == 0) ? x0 : (blockIdx.y == 1) ? x1 : x2;
    uint2* h = (blockIdx.y == 0) ? h0 : (blockIdx.y == 1) ? h1 : h2;
    uint2* l = (blockIdx.y == 0) ? l0 : (blockIdx.y == 1) ? l1 : l2;
    float4 v[4];
#pragma unroll
    for (int r = 0; r < 4; ++r) v[r] = x[base + r * 256];
#pragma unroll
    for (int r = 0; r < 4; ++r) {
        uint2 hh, ll;
        split2(v[r].x, v[r].y, hh.x, ll.x);
        split2(v[r].z, v[r].w, hh.y, ll.y);
        h[base + r * 256] = hh;
        l[base + r * 256] = ll;
    }
}
__global__ void splitw_kernel(const float4* __restrict__ wq, const float4* __restrict__ wk,
                              const float4* __restrict__ wv, const float4* __restrict__ wo,
                              uint2* __restrict__ qkvh, uint2* __restrict__ qkvl,
                              uint2* __restrict__ woh, uint2* __restrict__ wol, int n4) {
    int i = blockIdx.x * 256 + threadIdx.x;
    if (i >= n4) return;
    int y = blockIdx.y;
    const float4* src = (y == 0) ? wq : (y == 1) ? wk : (y == 2) ? wv : wo;
    float4 v = src[i];
    if (y == 0) { v.x *= QSCALE; v.y *= QSCALE; v.z *= QSCALE; v.w *= QSCALE; }
    uint2 hh, ll;
    split2(v.x, v.y, hh.x, ll.x);
    split2(v.z, v.w, hh.y, ll.y);
    uint2* h = (y < 3) ? (qkvh + (size_t)y * n4) : woh;
    uint2* l = (y < 3) ? (qkvl + (size_t)y * n4) : wol;
    h[i] = hh; l[i] = ll;
}
__global__ void maskbits_kernel(const int* __restrict__ m, uint32_t* __restrict__ bits) {
    size_t w = (size_t)blockIdx.x * 8 + (threadIdx.x >> 5);
    int lane = threadIdx.x & 31;
    const int* p = m + w * 128;
    int v0 = p[lane], v1 = p[lane + 32], v2 = p[lane + 64], v3 = p[lane + 96];
    uint32_t b0 = __ballot_sync(0xffffffffu, v0 != 0);
    uint32_t b1 = __ballot_sync(0xffffffffu, v1 != 0);
    uint32_t b2 = __ballot_sync(0xffffffffu, v2 != 0);
    uint32_t b3 = __ballot_sync(0xffffffffu, v3 != 0);
    if (lane == 0) { bits[w*4] = b0; bits[w*4+1] = b1; bits[w*4+2] = b2; bits[w*4+3] = b3; }
}

// ---------------- GEMM: 128x128 tile, 2 CTAs/SM, 2-stage (R10 proven) -------
#define GST 40
#define G_AH 0
#define G_AL (128*GST)
#define G_WH (2*128*GST)
#define G_WL (3*128*GST)
#define GSTAGE (4*128*GST)

__global__ __launch_bounds__(256, 2) void gemm_mma(
    const __nv_bfloat16* __restrict__ A0h, const __nv_bfloat16* __restrict__ A0l,
    const __nv_bfloat16* __restrict__ A1h, const __nv_bfloat16* __restrict__ A1l,
    const __nv_bfloat16* __restrict__ A2h, const __nv_bfloat16* __restrict__ A2l,
    const __nv_bfloat16* __restrict__ Wh, const __nv_bfloat16* __restrict__ Wl,
    float* __restrict__ Cf, __nv_bfloat16* __restrict__ Ch, __nv_bfloat16* __restrict__ Cl,
    int N, int K, int split_out)
{
    extern __shared__ __align__(16) __nv_bfloat16 sg[];

    const int tid = threadIdx.x, lane = tid & 31, w = tid >> 5;
    const int g = lane >> 2, t4 = lane & 3, l15 = lane & 15;
    const int m0 = (w >> 2) * 64, n0 = (w & 3) * 32;
    const int bm = blockIdx.y * 128, bn = blockIdx.x * 128;

    const int sel = bn >> 10;
    const __nv_bfloat16* Ah = (sel == 0) ? A0h : (sel == 1) ? A1h : A2h;
    const __nv_bfloat16* Al = (sel == 0) ? A0l : (sel == 1) ? A1l : A2l;

    const __nv_bfloat16* pAh = Ah + (size_t)bm * K;
    const __nv_bfloat16* pAl = Al + (size_t)bm * K;
    const __nv_bfloat16* pWh = Wh + (size_t)bn * K;
    const __nv_bfloat16* pWl = Wl + (size_t)bn * K;

    auto stage = [&](int buf, int k0) {
        __nv_bfloat16* st = sg + buf * GSTAGE;
#pragma unroll
        for (int it = 0; it < 8; ++it) {
            int c = it * 256 + tid;
            int mat = c >> 9, r = (c >> 2) & 127, u = c & 3;
            const __nv_bfloat16* src =
                (mat == 0 ? pAh : mat == 1 ? pAl : mat == 2 ? pWh : pWl)
                + (size_t)r * K + k0 + u * 8;
            cp16(st + mat * (128 * GST) + r * GST + u * 8, src);
        }
    };

    float acc[4][4][4];
#pragma unroll
    for (int i = 0; i < 4; ++i)
#pragma unroll
        for (int j = 0; j < 4; ++j)
#pragma unroll
            for (int c = 0; c < 4; ++c) acc[i][j][c] = 0.f;

    const int NST = K / 32;
    stage(0, 0); CP_COMMIT();

    for (int kt = 0; kt < NST; ++kt) {
        const int buf = kt & 1;
        if (kt + 1 < NST) { stage(buf ^ 1, (kt + 1) * 32); CP_COMMIT(); CP_WAIT(1); }
        else CP_WAIT(0);
        __syncthreads();

        const __nv_bfloat16* st = sg + buf * GSTAGE;
#pragma unroll
        for (int ks = 0; ks < 32; ks += 16) {
            uint32_t wh[2][4], wl[2][4];
            {
                const int ro0 = (n0 + l15) * GST + ks + (lane >> 4) * 8;
                const int ro1 = (n0 + 16 + l15) * GST + ks + (lane >> 4) * 8;
                ldsm_x4(wh[0], st + G_WH + ro0);
                ldsm_x4(wl[0], st + G_WL + ro0);
                ldsm_x4(wh[1], st + G_WH + ro1);
                ldsm_x4(wl[1], st + G_WL + ro1);
            }
            uint32_t ah[2][4], al[2][4];
            {
                const int ro = (m0 + l15) * GST + ks + (lane >> 4) * 8;
                ldsm_x4(ah[0], st + G_AH + ro);
                ldsm_x4(al[0], st + G_AL + ro);
            }
#pragma unroll
            for (int mt = 0; mt < 4; ++mt) {
                const int cur = mt & 1;
                if (mt < 3) {
                    const int ro = (m0 + (mt + 1) * 16 + l15) * GST + ks + (lane >> 4) * 8;
                    ldsm_x4(ah[cur ^ 1], st + G_AH + ro);
                    ldsm_x4(al[cur ^ 1], st + G_AL + ro);
                }
#pragma unroll
                for (int nn = 0; nn < 2; ++nn) {
                    uint32_t bhe[2] = {wh[nn][0], wh[nn][2]}, bho[2] = {wh[nn][1], wh[nn][3]};
                    uint32_t ble[2] = {wl[nn][0], wl[nn][2]}, blo[2] = {wl[nn][1], wl[nn][3]};
                    mma16816(acc[mt][2*nn],   ah[cur], bhe);
                    mma16816(acc[mt][2*nn+1], ah[cur], bho);
                    mma16816(acc[mt][2*nn],   ah[cur], ble);
                    mma16816(acc[mt][2*nn+1], ah[cur], blo);
                    mma16816(acc[mt][2*nn],   al[cur], bhe);
                    mma16816(acc[mt][2*nn+1], al[cur], bho);
                }
            }
        }
        __syncthreads();
    }

#pragma unroll
    for (int mt = 0; mt < 4; ++mt)
#pragma unroll
        for (int nt = 0; nt < 4; ++nt) {
            int row = bm + m0 + mt * 16 + g;
            int col = bn + n0 + nt * 8 + 2 * t4;
            if (split_out) {
                uint32_t hh, ll;
                split2(acc[mt][nt][0], acc[mt][nt][1], hh, ll);
                *(uint32_t*)&Ch[(size_t)row * N + col] = hh;
                *(uint32_t*)&Cl[(size_t)row * N + col] = ll;
                split2(acc[mt][nt][2], acc[mt][nt][3], hh, ll);
                *(uint32_t*)&Ch[(size_t)(row + 8) * N + col] = hh;
                *(uint32_t*)&Cl[(size_t)(row + 8) * N + col] = ll;
            } else {
                *(float2*)(Cf + (size_t)row * N + col) =
                    make_float2(acc[mt][nt][0], acc[mt][nt][1]);
                *(float2*)(Cf + (size_t)(row + 8) * N + col) =
                    make_float2(acc[mt][nt][2], acc[mt][nt][3]);
            }
        }
}

// ---------------- attention: 128-query tile, 8 warps (R10 verbatim) ---------
#define TS 72
#define A_QH 0
#define A_QL (128*TS)
#define A_KV (2*128*TS)
#define A_KVSZ (4*64*TS)

__global__ __launch_bounds__(256) void attn_tc(
    const __nv_bfloat16* __restrict__ QKVh, const __nv_bfloat16* __restrict__ QKVl,
    const uint32_t* __restrict__ mbits,
    __nv_bfloat16* __restrict__ Oh, __nv_bfloat16* __restrict__ Ol)
{
    extern __shared__ __align__(16) __nv_bfloat16 sm[];

    const int b = blockIdx.z, h = blockIdx.y, s0 = blockIdx.x * 128;
    const int tid = threadIdx.x, lane = tid & 31, w = tid >> 5;
    const int g = lane >> 2, t4 = lane & 3;
    const int m0 = w * 16, l15 = lane & 15;

    const __nv_bfloat16* qhp = QKVh + (size_t)(b * SS + s0) * NQKV + h * 64;
    const __nv_bfloat16* qlp = QKVl + (size_t)(b * SS + s0) * NQKV + h * 64;
#pragma unroll
    for (int it = 0; it < 8; ++it) {
        int c = it * 256 + tid;
        int r = (c & 1023) >> 3, u = c & 7;
        if (c < 1024) cp16(&sm[A_QH + r * TS + u * 8], qhp + (size_t)r * NQKV + u * 8);
        else          cp16(&sm[A_QL + r * TS + u * 8], qlp + (size_t)r * NQKV + u * 8);
    }

    const __nv_bfloat16* khp = QKVh + (size_t)(b * SS) * NQKV + DD + h * 64;
    const __nv_bfloat16* klp = QKVl + (size_t)(b * SS) * NQKV + DD + h * 64;
    const __nv_bfloat16* vhp = QKVh + (size_t)(b * SS) * NQKV + 2 * DD + h * 64;
    const __nv_bfloat16* vlp = QKVl + (size_t)(b * SS) * NQKV + 2 * DD + h * 64;

    auto stageKV = [&](int buf, int t0) {
        __nv_bfloat16* st = sm + A_KV + buf * A_KVSZ;
#pragma unroll
        for (int it = 0; it < 8; ++it) {
            int c = it * 256 + tid;
            int mat = c >> 9, r = (c >> 3) & 63, u = c & 7;
            const __nv_bfloat16* src =
                (mat == 0 ? khp : mat == 1 ? klp : mat == 2 ? vhp : vlp)
                + (size_t)(t0 + r) * NQKV + u * 8;
            cp16(st + mat * (64 * TS) + r * TS + u * 8, src);
        }
    };

    stageKV(0, 0);
    CP_COMMIT();

    float m_i[2] = {-1e30f, -1e30f}, l_i[2] = {0.f, 0.f};
    float oacc[8][4];
#pragma unroll
    for (int nt = 0; nt < 8; ++nt)
#pragma unroll
        for (int c = 0; c < 4; ++c) oacc[nt][c] = 0.f;

    const uint32_t* mb0 = mbits + ((size_t)b * SS + s0 + m0 + g) * (SS / 32);
    const uint32_t* mb8 = mb0 + 8 * (SS / 32);

    for (int i = 0; i < SS / 64; ++i) {
        const int t0 = i * 64, buf = i & 1;
        __syncthreads();
        if (i + 1 < SS / 64) { stageKV(buf ^ 1, t0 + 64); CP_COMMIT(); CP_WAIT(1); }
        else CP_WAIT(0);
        __syncthreads();

        const __nv_bfloat16* bKh = sm + A_KV + buf * A_KVSZ;
        const __nv_bfloat16* bKl = bKh + 64 * TS;
        const __nv_bfloat16* bVh = bKl + 64 * TS;
        const __nv_bfloat16* bVl = bVh + 64 * TS;

        float sc[8][4];
#pragma unroll
        for (int nt = 0; nt < 8; ++nt)
#pragma unroll
            for (int c = 0; c < 4; ++c) sc[nt][c] = 0.f;

#pragma unroll
        for (int ks = 0; ks < 64; ks += 16) {
            uint32_t qfh[4], qfl[4];
            const int qo = (m0 + l15) * TS + ks + (lane >> 4) * 8;
            ldsm_x4(qfh, &sm[A_QH + qo]);
            ldsm_x4(qfl, &sm[A_QL + qo]);

            uint32_t kh4[2][4], kl4[2][4];
            {
                const int ro = (l15) * TS + ks + (lane >> 4) * 8;
                ldsm_x4(kh4[0], bKh + ro);
                ldsm_x4(kl4[0], bKl + ro);
            }
#pragma unroll
            for (int nt2 = 0; nt2 < 4; ++nt2) {
                const int cur = nt2 & 1;
                if (nt2 < 3) {
                    const int ro = ((nt2 + 1) * 16 + l15) * TS + ks + (lane >> 4) * 8;
                    ldsm_x4(kh4[cur ^ 1], bKh + ro);
                    ldsm_x4(kl4[cur ^ 1], bKl + ro);
                }
                uint32_t bhe[2] = {kh4[cur][0], kh4[cur][2]}, bho[2] = {kh4[cur][1], kh4[cur][3]};
                uint32_t ble[2] = {kl4[cur][0], kl4[cur][2]}, blo[2] = {kl4[cur][1], kl4[cur][3]};
                mma16816(sc[2*nt2],   qfh, bhe);
                mma16816(sc[2*nt2+1], qfh, bho);
                mma16816(sc[2*nt2],   qfh, ble);
                mma16816(sc[2*nt2+1], qfh, blo);
                mma16816(sc[2*nt2],   qfl, bhe);
                mma16816(sc[2*nt2+1], qfl, bho);
            }
        }

        uint32_t wa0 = mb0[t0 >> 5], wb0 = mb0[(t0 >> 5) + 1];
        uint32_t wa8 = mb8[t0 >> 5], wb8 = mb8[(t0 >> 5) + 1];
        if ((wa0 & wb0 & wa8 & wb8) != 0xffffffffu) {
#pragma unroll
            for (int nt = 0; nt < 8; ++nt) {
                int c = nt * 8 + 2 * t4;
                uint32_t s0w = (c & 32) ? wb0 : wa0;
                uint32_t s8w = (c & 32) ? wb8 : wa8;
                int sh = c & 31;
                if (!((s0w >> sh) & 1))       sc[nt][0] = -1e10f;
                if (!((s0w >> (sh + 1)) & 1)) sc[nt][1] = -1e10f;
                if (!((s8w >> sh) & 1))       sc[nt][2] = -1e10f;
                if (!((s8w >> (sh + 1)) & 1)) sc[nt][3] = -1e10f;
            }
        }

        float mx0 = -1e30f, mx1 = -1e30f;
#pragma unroll
        for (int nt = 0; nt < 8; ++nt) {
            mx0 = fmaxf(mx0, fmaxf(sc[nt][0], sc[nt][1]));
            mx1 = fmaxf(mx1, fmaxf(sc[nt][2], sc[nt][3]));
        }
        mx0 = fmaxf(mx0, __shfl_xor_sync(0xffffffffu, mx0, 1));
        mx0 = fmaxf(mx0, __shfl_xor_sync(0xffffffffu, mx0, 2));
        mx1 = fmaxf(mx1, __shfl_xor_sync(0xffffffffu, mx1, 1));
        mx1 = fmaxf(mx1, __shfl_xor_sync(0xffffffffu, mx1, 2));

        float mn0 = fmaxf(m_i[0], mx0), mn1 = fmaxf(m_i[1], mx1);
        float corr0 = exp2f(m_i[0] - mn0), corr1 = exp2f(m_i[1] - mn1);
        m_i[0] = mn0; m_i[1] = mn1;

        float sum0 = 0.f, sum1 = 0.f;
#pragma unroll
        for (int nt = 0; nt < 8; ++nt) {
            sc[nt][0] = exp2f(sc[nt][0] - mn0);
            sc[nt][1] = exp2f(sc[nt][1] - mn0);
            sc[nt][2] = exp2f(sc[nt][2] - mn1);
            sc[nt][3] = exp2f(sc[nt][3] - mn1);
            sum0 += sc[nt][0] + sc[nt][1];
            sum1 += sc[nt][2] + sc[nt][3];
        }
        sum0 += __shfl_xor_sync(0xffffffffu, sum0, 1);
        sum0 += __shfl_xor_sync(0xffffffffu, sum0, 2);
        sum1 += __shfl_xor_sync(0xffffffffu, sum1, 1);
        sum1 += __shfl_xor_sync(0xffffffffu, sum1, 2);
        l_i[0] = l_i[0] * corr0 + sum0;
        l_i[1] = l_i[1] * corr1 + sum1;
#pragma unroll
        for (int nt = 0; nt < 8; ++nt) {
            oacc[nt][0] *= corr0; oacc[nt][1] *= corr0;
            oacc[nt][2] *= corr1; oacc[nt][3] *= corr1;
        }

#pragma unroll
        for (int j = 0; j < 4; ++j) {
            uint32_t ph[4], pl[4];
            split2(sc[2*j][0],   sc[2*j][1],   ph[0], pl[0]);
            split2(sc[2*j][2],   sc[2*j][3],   ph[1], pl[1]);
            split2(sc[2*j+1][0], sc[2*j+1][1], ph[2], pl[2]);
            split2(sc[2*j+1][2], sc[2*j+1][3], ph[3], pl[3]);

            uint32_t vh4[2][4], vl4[2][4];
            {
                const int ro = (j * 16 + l15) * TS + (lane >> 4) * 8;
                ldsm_x4t(vh4[0], bVh + ro);
                ldsm_x4t(vl4[0], bVl + ro);
            }
#pragma unroll
            for (int nt2 = 0; nt2 < 4; ++nt2) {
                const int cur = nt2 & 1;
                if (nt2 < 3) {
                    const int ro = (j * 16 + l15) * TS + (nt2 + 1) * 16 + (lane >> 4) * 8;
                    ldsm_x4t(vh4[cur ^ 1], bVh + ro);
                    ldsm_x4t(vl4[cur ^ 1], bVl + ro);
                }
                uint32_t vhe[2] = {vh4[cur][0], vh4[cur][1]}, vho[2] = {vh4[cur][2], vh4[cur][3]};
                uint32_t vle[2] = {vl4[cur][0], vl4[cur][1]}, vlo[2] = {vl4[cur][2], vl4[cur][3]};
                mma16816(oacc[2*nt2],   ph, vhe);
                mma16816(oacc[2*nt2+1], ph, vho);
                mma16816(oacc[2*nt2],   ph, vle);
                mma16816(oacc[2*nt2+1], ph, vlo);
                mma16816(oacc[2*nt2],   pl, vhe);
                mma16816(oacc[2*nt2+1], pl, vho);
            }
        }
    }

    float inv0 = __fdividef(1.f, l_i[0]);
    float inv1 = __fdividef(1.f, l_i[1]);
    size_t r0 = (size_t)(b * SS + s0 + m0 + g) * DD + h * 64;
    size_t r8 = r0 + (size_t)8 * DD;
#pragma unroll
    for (int nt = 0; nt < 8; ++nt) {
        int col = nt * 8 + 2 * t4;
        uint32_t hh, ll;
        split2(oacc[nt][0] * inv0, oacc[nt][1] * inv0, hh, ll);
        *(uint32_t*)&Oh[r0 + col] = hh; *(uint32_t*)&Ol[r0 + col] = ll;
        split2(oacc[nt][2] * inv1, oacc[nt][3] * inv1, hh, ll);
        *(uint32_t*)&Oh[r8 + col] = hh; *(uint32_t*)&Ol[r8 + col] = ll;
    }
}

// ---------------------------------------------------------------------------
extern "C" void kernel_launch(void* const* d_in, const int* in_sizes, int n_in,
                              void* d_out, int out_size)
{
    const float* queries = (const float*)d_in[0];
    const float* keys    = (const float*)d_in[1];
    const float* values  = (const float*)d_in[2];
    const int*   mask    = (const int*)  d_in[3];
    const float* Wq = (const float*)d_in[4];
    const float* Wk = (const float*)d_in[5];
    const float* Wv = (const float*)d_in[6];
    const float* Wo = (const float*)d_in[7];
    float* out = (float*)d_out;

    __nv_bfloat16 *xqh,*xql,*xkh,*xkl,*xvh,*xvl, *wqkvh,*wqkvl,*woh,*wol;
    __nv_bfloat16 *qkvh,*qkvl,*oh,*ol;
    uint32_t* mb;
    cudaGetSymbolAddress((void**)&xqh, g_xqh);   cudaGetSymbolAddress((void**)&xql, g_xql);
    cudaGetSymbolAddress((void**)&xkh, g_xkh);   cudaGetSymbolAddress((void**)&xkl, g_xkl);
    cudaGetSymbolAddress((void**)&xvh, g_xvh);   cudaGetSymbolAddress((void**)&xvl, g_xvl);
    cudaGetSymbolAddress((void**)&wqkvh, g_wqkvh); cudaGetSymbolAddress((void**)&wqkvl, g_wqkvl);
    cudaGetSymbolAddress((void**)&woh, g_woh);   cudaGetSymbolAddress((void**)&wol, g_wol);
    cudaGetSymbolAddress((void**)&qkvh, g_qkvh); cudaGetSymbolAddress((void**)&qkvl, g_qkvl);
    cudaGetSymbolAddress((void**)&oh, g_oh);     cudaGetSymbolAddress((void**)&ol, g_ol);
    cudaGetSymbolAddress((void**)&mb, g_mbits);

    const int GEMM_SMEM = 2 * GSTAGE * (int)sizeof(__nv_bfloat16);                  // 81920
    cudaFuncSetAttribute(gemm_mma, cudaFuncAttributeMaxDynamicSharedMemorySize, GEMM_SMEM);
    const int ATTN_SMEM = (2 * 128 * TS + 2 * A_KVSZ) * (int)sizeof(__nv_bfloat16); // 110592
    cudaFuncSetAttribute(attn_tc, cudaFuncAttributeMaxDynamicSharedMemorySize, ATTN_SMEM);

    const int n4i = MTOK * DD / 4, n4w = DD * DD / 4;
    split3_kernel<<<dim3(n4i / 1024, 3), 256>>>(
        (const float4*)queries, (const float4*)keys, (const float4*)values,
        (uint2*)xqh, (uint2*)xql, (uint2*)xkh, (uint2*)xkl, (uint2*)xvh, (uint2*)xvl, n4i);
    splitw_kernel<<<dim3(n4w / 256, 4), 256>>>(
        (const float4*)Wq, (const float4*)Wk, (const float4*)Wv, (const float4*)Wo,
        (uint2*)wqkvh, (uint2*)wqkvl, (uint2*)woh, (uint2*)wol, n4w);
    maskbits_kernel<<<(int)((size_t)BB * SS * SS / 128 / 8), 256>>>(mask, mb);

    gemm_mma<<<dim3(NQKV / 128, MTOK / 128), 256, GEMM_SMEM>>>(
        xqh, xql, xkh, xkl, xvh, xvl, wqkvh, wqkvl,
        nullptr, qkvh, qkvl, NQKV, DD, 1);

    attn_tc<<<dim3(SS / 128, HH, BB), 256, ATTN_SMEM>>>(qkvh, qkvl, mb, oh, ol);

    gemm_mma<<<dim3(DD / 128, MTOK / 128), 256, GEMM_SMEM>>>(
        oh, ol, oh, ol, oh, ol, woh, wol,
        out, nullptr, nullptr, DD, DD, 0);
}

// round 15
// speedup vs baseline: 1.2569x; 1.1773x over previous
#include <cuda_runtime.h>
#include <cuda_fp16.h>
#include <cstdint>
#include <cstddef>

#define BB 4
#define SS 2048
#define DD 1024
#define HH 16
#define MTOK (BB*SS)
#define NQKV (3*DD)
#define QSCALE 0.1803368801111204f   // 0.125 * log2(e)

// ---------------- scratch (__device__ globals; allocs forbidden) ----------
__device__ __half g_xqh[MTOK*DD], g_xql[MTOK*DD];
__device__ __half g_xkh[MTOK*DD], g_xkl[MTOK*DD];
__device__ __half g_xvh[MTOK*DD], g_xvl[MTOK*DD];
__device__ __half g_wqkvh[3*DD*DD];
__device__ __half g_woh[DD*DD];
__device__ __half g_qkvh[(size_t)MTOK*NQKV], g_qkvl[(size_t)MTOK*NQKV];
__device__ __half g_oh[MTOK*DD], g_ol[MTOK*DD];
__device__ uint32_t g_mbits[(size_t)BB*SS*(SS/32)];

// ---------------- helpers --------------------------------------------------
__device__ __forceinline__ uint32_t smem_u32(const void* p) {
    return (uint32_t)__cvta_generic_to_shared(p);
}
__device__ __forceinline__ void mma16816h(float* c, const uint32_t* a, const uint32_t* b) {
    asm volatile(
        "mma.sync.aligned.m16n8k16.row.col.f32.f16.f16.f32 "
        "{%0,%1,%2,%3},{%4,%5,%6,%7},{%8,%9},{%0,%1,%2,%3};"
        : "+f"(c[0]), "+f"(c[1]), "+f"(c[2]), "+f"(c[3])
        : "r"(a[0]), "r"(a[1]), "r"(a[2]), "r"(a[3]), "r"(b[0]), "r"(b[1]));
}
__device__ __forceinline__ void ldsm_x4(uint32_t* r, const void* p) {
    uint32_t a = smem_u32(p);
    asm volatile("ldmatrix.sync.aligned.m8n8.x4.shared.b16 {%0,%1,%2,%3},[%4];"
                 : "=r"(r[0]), "=r"(r[1]), "=r"(r[2]), "=r"(r[3]) : "r"(a));
}
__device__ __forceinline__ void ldsm_x4t(uint32_t* r, const void* p) {
    uint32_t a = smem_u32(p);
    asm volatile("ldmatrix.sync.aligned.m8n8.x4.trans.shared.b16 {%0,%1,%2,%3},[%4];"
                 : "=r"(r[0]), "=r"(r[1]), "=r"(r[2]), "=r"(r[3]) : "r"(a));
}
// fp16 2-way split: x = hi + lo, hi = fp16(x) (11-bit mantissa)
__device__ __forceinline__ void split2h(float f0, float f1, uint32_t& hi, uint32_t& lo) {
    __half2 h = __floats2half2_rn(f0, f1);
    float r0 = f0 - __half2float(__low2half(h));
    float r1 = f1 - __half2float(__high2half(h));
    hi = *reinterpret_cast<uint32_t*>(&h);
    __half2 l = __floats2half2_rn(r0, r1);
    lo = *reinterpret_cast<uint32_t*>(&l);
}
__device__ __forceinline__ void cp16(void* s, const void* g) {
    uint32_t sa = smem_u32(s);
    asm volatile("cp.async.cg.shared.global [%0], [%1], 16;" :: "r"(sa), "l"(g));
}
#define CP_COMMIT() asm volatile("cp.async.commit_group;" ::: "memory")
#define CP_WAIT(n)  asm volatile("cp.async.wait_group %0;" :: "n"(n) : "memory")

// ---------------- prepass kernels ------------------------------------------
__global__ void split3_kernel(const float4* __restrict__ x0, const float4* __restrict__ x1,
                              const float4* __restrict__ x2,
                              uint2* __restrict__ h0, uint2* __restrict__ l0,
                              uint2* __restrict__ h1, uint2* __restrict__ l1,
                              uint2* __restrict__ h2, uint2* __restrict__ l2, int n4) {
    int base = blockIdx.x * 1024 + threadIdx.x;
    const float4* x = (blockIdx.y == 0) ? x0 : (blockIdx.y == 1) ? x1 : x2;
    uint2* h = (blockIdx.y == 0) ? h0 : (blockIdx.y == 1) ? h1 : h2;
    uint2* l = (blockIdx.y == 0) ? l0 : (blockIdx.y == 1) ? l1 : l2;
    float4 v[4];
#pragma unroll
    for (int r = 0; r < 4; ++r) v[r] = x[base + r * 256];
#pragma unroll
    for (int r = 0; r < 4; ++r) {
        uint2 hh, ll;
        split2h(v[r].x, v[r].y, hh.x, ll.x);
        split2h(v[r].z, v[r].w, hh.y, ll.y);
        h[base + r * 256] = hh;
        l[base + r * 256] = ll;
    }
}
// weight to fp16 hi only (lo term dropped by design): y=0 Wq*QSCALE,1 Wk,2 Wv,3 Wo
__global__ void splitw_kernel(const float4* __restrict__ wq, const float4* __restrict__ wk,
                              const float4* __restrict__ wv, const float4* __restrict__ wo,
                              uint2* __restrict__ qkvh, uint2* __restrict__ woh, int n4) {
    int i = blockIdx.x * 256 + threadIdx.x;
    if (i >= n4) return;
    int y = blockIdx.y;
    const float4* src = (y == 0) ? wq : (y == 1) ? wk : (y == 2) ? wv : wo;
    float4 v = src[i];
    if (y == 0) { v.x *= QSCALE; v.y *= QSCALE; v.z *= QSCALE; v.w *= QSCALE; }
    __half2 a = __floats2half2_rn(v.x, v.y);
    __half2 b = __floats2half2_rn(v.z, v.w);
    uint2 hh;
    hh.x = *reinterpret_cast<uint32_t*>(&a);
    hh.y = *reinterpret_cast<uint32_t*>(&b);
    uint2* h = (y < 3) ? (qkvh + (size_t)y * n4) : woh;
    h[i] = hh;
}
__global__ void maskbits_kernel(const int* __restrict__ m, uint32_t* __restrict__ bits) {
    size_t w = (size_t)blockIdx.x * 8 + (threadIdx.x >> 5);
    int lane = threadIdx.x & 31;
    const int* p = m + w * 128;
    int v0 = p[lane], v1 = p[lane + 32], v2 = p[lane + 64], v3 = p[lane + 96];
    uint32_t b0 = __ballot_sync(0xffffffffu, v0 != 0);
    uint32_t b1 = __ballot_sync(0xffffffffu, v1 != 0);
    uint32_t b2 = __ballot_sync(0xffffffffu, v2 != 0);
    uint32_t b3 = __ballot_sync(0xffffffffu, v3 != 0);
    if (lane == 0) { bits[w*4] = b0; bits[w*4+1] = b1; bits[w*4+2] = b2; bits[w*4+3] = b3; }
}

// ---------------- GEMM: C = (Ah+Al) * Wh^T, fp16, 2 mmas per product --------
// 128x128 tile, 2 CTAs/SM, 2-stage; 3 staged matrices (Ah, Al, Wh).
#define GST 40
#define G_AH 0
#define G_AL (128*GST)
#define G_WH (2*128*GST)
#define GSTAGE (3*128*GST)   // 15360 halves = 30720 B per stage

__global__ __launch_bounds__(256, 2) void gemm_mma(
    const __half* __restrict__ A0h, const __half* __restrict__ A0l,
    const __half* __restrict__ A1h, const __half* __restrict__ A1l,
    const __half* __restrict__ A2h, const __half* __restrict__ A2l,
    const __half* __restrict__ Wh,
    float* __restrict__ Cf, __half* __restrict__ Ch, __half* __restrict__ Cl,
    int N, int K, int split_out)
{
    extern __shared__ __align__(16) __half sg[];

    const int tid = threadIdx.x, lane = tid & 31, w = tid >> 5;
    const int g = lane >> 2, t4 = lane & 3, l15 = lane & 15;
    const int m0 = (w >> 2) * 64, n0 = (w & 3) * 32;
    const int bm = blockIdx.y * 128, bn = blockIdx.x * 128;

    const int sel = bn >> 10;
    const __half* Ah = (sel == 0) ? A0h : (sel == 1) ? A1h : A2h;
    const __half* Al = (sel == 0) ? A0l : (sel == 1) ? A1l : A2l;

    const __half* pAh = Ah + (size_t)bm * K;
    const __half* pAl = Al + (size_t)bm * K;
    const __half* pWh = Wh + (size_t)bn * K;

    // staging: 3 matrices x 128 rows x 32 cols; 1536 cp16, 6 per thread
    auto stage = [&](int buf, int k0) {
        __half* st = sg + buf * GSTAGE;
#pragma unroll
        for (int it = 0; it < 6; ++it) {
            int c = it * 256 + tid;            // 0..1535
            int mat = c >> 9, r = (c >> 2) & 127, u = c & 3;
            const __half* src =
                (mat == 0 ? pAh : mat == 1 ? pAl : pWh) + (size_t)r * K + k0 + u * 8;
            cp16(st + mat * (128 * GST) + r * GST + u * 8, src);
        }
    };

    float acc[4][4][4];
#pragma unroll
    for (int i = 0; i < 4; ++i)
#pragma unroll
        for (int j = 0; j < 4; ++j)
#pragma unroll
            for (int c = 0; c < 4; ++c) acc[i][j][c] = 0.f;

    const int NST = K / 32;
    stage(0, 0); CP_COMMIT();

    for (int kt = 0; kt < NST; ++kt) {
        const int buf = kt & 1;
        if (kt + 1 < NST) { stage(buf ^ 1, (kt + 1) * 32); CP_COMMIT(); CP_WAIT(1); }
        else CP_WAIT(0);
        __syncthreads();

        const __half* st = sg + buf * GSTAGE;
#pragma unroll
        for (int ks = 0; ks < 32; ks += 16) {
            uint32_t wh[2][4];
            {
                const int ro0 = (n0 + l15) * GST + ks + (lane >> 4) * 8;
                const int ro1 = (n0 + 16 + l15) * GST + ks + (lane >> 4) * 8;
                ldsm_x4(wh[0], st + G_WH + ro0);
                ldsm_x4(wh[1], st + G_WH + ro1);
            }
            uint32_t ah[2][4], al[2][4];
            {
                const int ro = (m0 + l15) * GST + ks + (lane >> 4) * 8;
                ldsm_x4(ah[0], st + G_AH + ro);
                ldsm_x4(al[0], st + G_AL + ro);
            }
#pragma unroll
            for (int mt = 0; mt < 4; ++mt) {
                const int cur = mt & 1;
                if (mt < 3) {
                    const int ro = (m0 + (mt + 1) * 16 + l15) * GST + ks + (lane >> 4) * 8;
                    ldsm_x4(ah[cur ^ 1], st + G_AH + ro);
                    ldsm_x4(al[cur ^ 1], st + G_AL + ro);
                }
#pragma unroll
                for (int nn = 0; nn < 2; ++nn) {
                    uint32_t bhe[2] = {wh[nn][0], wh[nn][2]}, bho[2] = {wh[nn][1], wh[nn][3]};
                    mma16816h(acc[mt][2*nn],   ah[cur], bhe);
                    mma16816h(acc[mt][2*nn+1], ah[cur], bho);
                    mma16816h(acc[mt][2*nn],   al[cur], bhe);
                    mma16816h(acc[mt][2*nn+1], al[cur], bho);
                }
            }
        }
        __syncthreads();
    }

#pragma unroll
    for (int mt = 0; mt < 4; ++mt)
#pragma unroll
        for (int nt = 0; nt < 4; ++nt) {
            int row = bm + m0 + mt * 16 + g;
            int col = bn + n0 + nt * 8 + 2 * t4;
            if (split_out) {
                uint32_t hh, ll;
                split2h(acc[mt][nt][0], acc[mt][nt][1], hh, ll);
                *(uint32_t*)&Ch[(size_t)row * N + col] = hh;
                *(uint32_t*)&Cl[(size_t)row * N + col] = ll;
                split2h(acc[mt][nt][2], acc[mt][nt][3], hh, ll);
                *(uint32_t*)&Ch[(size_t)(row + 8) * N + col] = hh;
                *(uint32_t*)&Cl[(size_t)(row + 8) * N + col] = ll;
            } else {
                *(float2*)(Cf + (size_t)row * N + col) =
                    make_float2(acc[mt][nt][0], acc[mt][nt][1]);
                *(float2*)(Cf + (size_t)(row + 8) * N + col) =
                    make_float2(acc[mt][nt][2], acc[mt][nt][3]);
            }
        }
}

// ---------------- attention: 128-query tile, 8 warps (R10 shape, fp16) ------
#define TS 72
#define A_QH 0
#define A_QL (128*TS)
#define A_KV (2*128*TS)
#define A_KVSZ (4*64*TS)

__global__ __launch_bounds__(256) void attn_tc(
    const __half* __restrict__ QKVh, const __half* __restrict__ QKVl,
    const uint32_t* __restrict__ mbits,
    __half* __restrict__ Oh, __half* __restrict__ Ol)
{
    extern __shared__ __align__(16) __half sm[];

    const int b = blockIdx.z, h = blockIdx.y, s0 = blockIdx.x * 128;
    const int tid = threadIdx.x, lane = tid & 31, w = tid >> 5;
    const int g = lane >> 2, t4 = lane & 3;
    const int m0 = w * 16, l15 = lane & 15;

    const __half* qhp = QKVh + (size_t)(b * SS + s0) * NQKV + h * 64;
    const __half* qlp = QKVl + (size_t)(b * SS + s0) * NQKV + h * 64;
#pragma unroll
    for (int it = 0; it < 8; ++it) {
        int c = it * 256 + tid;
        int r = (c & 1023) >> 3, u = c & 7;
        if (c < 1024) cp16(&sm[A_QH + r * TS + u * 8], qhp + (size_t)r * NQKV + u * 8);
        else          cp16(&sm[A_QL + r * TS + u * 8], qlp + (size_t)r * NQKV + u * 8);
    }

    const __half* khp = QKVh + (size_t)(b * SS) * NQKV + DD + h * 64;
    const __half* klp = QKVl + (size_t)(b * SS) * NQKV + DD + h * 64;
    const __half* vhp = QKVh + (size_t)(b * SS) * NQKV + 2 * DD + h * 64;
    const __half* vlp = QKVl + (size_t)(b * SS) * NQKV + 2 * DD + h * 64;

    auto stageKV = [&](int buf, int t0) {
        __half* st = sm + A_KV + buf * A_KVSZ;
#pragma unroll
        for (int it = 0; it < 8; ++it) {
            int c = it * 256 + tid;
            int mat = c >> 9, r = (c >> 3) & 63, u = c & 7;
            const __half* src =
                (mat == 0 ? khp : mat == 1 ? klp : mat == 2 ? vhp : vlp)
                + (size_t)(t0 + r) * NQKV + u * 8;
            cp16(st + mat * (64 * TS) + r * TS + u * 8, src);
        }
    };

    stageKV(0, 0);
    CP_COMMIT();

    float m_i[2] = {-1e30f, -1e30f}, l_i[2] = {0.f, 0.f};
    float oacc[8][4];
#pragma unroll
    for (int nt = 0; nt < 8; ++nt)
#pragma unroll
        for (int c = 0; c < 4; ++c) oacc[nt][c] = 0.f;

    const uint32_t* mb0 = mbits + ((size_t)b * SS + s0 + m0 + g) * (SS / 32);
    const uint32_t* mb8 = mb0 + 8 * (SS / 32);

    for (int i = 0; i < SS / 64; ++i) {
        const int t0 = i * 64, buf = i & 1;
        __syncthreads();
        if (i + 1 < SS / 64) { stageKV(buf ^ 1, t0 + 64); CP_COMMIT(); CP_WAIT(1); }
        else CP_WAIT(0);
        __syncthreads();

        const __half* bKh = sm + A_KV + buf * A_KVSZ;
        const __half* bKl = bKh + 64 * TS;
        const __half* bVh = bKl + 64 * TS;
        const __half* bVl = bVh + 64 * TS;

        float sc[8][4];
#pragma unroll
        for (int nt = 0; nt < 8; ++nt)
#pragma unroll
            for (int c = 0; c < 4; ++c) sc[nt][c] = 0.f;

#pragma unroll
        for (int ks = 0; ks < 64; ks += 16) {
            uint32_t qfh[4], qfl[4];
            const int qo = (m0 + l15) * TS + ks + (lane >> 4) * 8;
            ldsm_x4(qfh, &sm[A_QH + qo]);
            ldsm_x4(qfl, &sm[A_QL + qo]);

            uint32_t kh4[2][4], kl4[2][4];
            {
                const int ro = (l15) * TS + ks + (lane >> 4) * 8;
                ldsm_x4(kh4[0], bKh + ro);
                ldsm_x4(kl4[0], bKl + ro);
            }
#pragma unroll
            for (int nt2 = 0; nt2 < 4; ++nt2) {
                const int cur = nt2 & 1;
                if (nt2 < 3) {
                    const int ro = ((nt2 + 1) * 16 + l15) * TS + ks + (lane >> 4) * 8;
                    ldsm_x4(kh4[cur ^ 1], bKh + ro);
                    ldsm_x4(kl4[cur ^ 1], bKl + ro);
                }
                uint32_t bhe[2] = {kh4[cur][0], kh4[cur][2]}, bho[2] = {kh4[cur][1], kh4[cur][3]};
                uint32_t ble[2] = {kl4[cur][0], kl4[cur][2]}, blo[2] = {kl4[cur][1], kl4[cur][3]};
                mma16816h(sc[2*nt2],   qfh, bhe);
                mma16816h(sc[2*nt2+1], qfh, bho);
                mma16816h(sc[2*nt2],   qfh, ble);
                mma16816h(sc[2*nt2+1], qfh, blo);
                mma16816h(sc[2*nt2],   qfl, bhe);
                mma16816h(sc[2*nt2+1], qfl, bho);
            }
        }

        uint32_t wa0 = mb0[t0 >> 5], wb0 = mb0[(t0 >> 5) + 1];
        uint32_t wa8 = mb8[t0 >> 5], wb8 = mb8[(t0 >> 5) + 1];
        if ((wa0 & wb0 & wa8 & wb8) != 0xffffffffu) {
#pragma unroll
            for (int nt = 0; nt < 8; ++nt) {
                int c = nt * 8 + 2 * t4;
                uint32_t s0w = (c & 32) ? wb0 : wa0;
                uint32_t s8w = (c & 32) ? wb8 : wa8;
                int sh = c & 31;
                if (!((s0w >> sh) & 1))       sc[nt][0] = -1e10f;
                if (!((s0w >> (sh + 1)) & 1)) sc[nt][1] = -1e10f;
                if (!((s8w >> sh) & 1))       sc[nt][2] = -1e10f;
                if (!((s8w >> (sh + 1)) & 1)) sc[nt][3] = -1e10f;
            }
        }

        float mx0 = -1e30f, mx1 = -1e30f;
#pragma unroll
        for (int nt = 0; nt < 8; ++nt) {
            mx0 = fmaxf(mx0, fmaxf(sc[nt][0], sc[nt][1]));
            mx1 = fmaxf(mx1, fmaxf(sc[nt][2], sc[nt][3]));
        }
        mx0 = fmaxf(mx0, __shfl_xor_sync(0xffffffffu, mx0, 1));
        mx0 = fmaxf(mx0, __shfl_xor_sync(0xffffffffu, mx0, 2));
        mx1 = fmaxf(mx1, __shfl_xor_sync(0xffffffffu, mx1, 1));
        mx1 = fmaxf(mx1, __shfl_xor_sync(0xffffffffu, mx1, 2));

        float mn0 = fmaxf(m_i[0], mx0), mn1 = fmaxf(m_i[1], mx1);
        float corr0 = exp2f(m_i[0] - mn0), corr1 = exp2f(m_i[1] - mn1);
        m_i[0] = mn0; m_i[1] = mn1;

        float sum0 = 0.f, sum1 = 0.f;
#pragma unroll
        for (int nt = 0; nt < 8; ++nt) {
            sc[nt][0] = exp2f(sc[nt][0] - mn0);
            sc[nt][1] = exp2f(sc[nt][1] - mn0);
            sc[nt][2] = exp2f(sc[nt][2] - mn1);
            sc[nt][3] = exp2f(sc[nt][3] - mn1);
            sum0 += sc[nt][0] + sc[nt][1];
            sum1 += sc[nt][2] + sc[nt][3];
        }
        sum0 += __shfl_xor_sync(0xffffffffu, sum0, 1);
        sum0 += __shfl_xor_sync(0xffffffffu, sum0, 2);
        sum1 += __shfl_xor_sync(0xffffffffu, sum1, 1);
        sum1 += __shfl_xor_sync(0xffffffffu, sum1, 2);
        l_i[0] = l_i[0] * corr0 + sum0;
        l_i[1] = l_i[1] * corr1 + sum1;
#pragma unroll
        for (int nt = 0; nt < 8; ++nt) {
            oacc[nt][0] *= corr0; oacc[nt][1] *= corr0;
            oacc[nt][2] *= corr1; oacc[nt][3] *= corr1;
        }

#pragma unroll
        for (int j = 0; j < 4; ++j) {
            uint32_t ph[4], pl[4];
            split2h(sc[2*j][0],   sc[2*j][1],   ph[0], pl[0]);
            split2h(sc[2*j][2],   sc[2*j][3],   ph[1], pl[1]);
            split2h(sc[2*j+1][0], sc[2*j+1][1], ph[2], pl[2]);
            split2h(sc[2*j+1][2], sc[2*j+1][3], ph[3], pl[3]);

            uint32_t vh4[2][4], vl4[2][4];
            {
                const int ro = (j * 16 + l15) * TS + (lane >> 4) * 8;
                ldsm_x4t(vh4[0], bVh + ro);
                ldsm_x4t(vl4[0], bVl + ro);
            }
#pragma unroll
            for (int nt2 = 0; nt2 < 4; ++nt2) {
                const int cur = nt2 & 1;
                if (nt2 < 3) {
                    const int ro = (j * 16 + l15) * TS + (nt2 + 1) * 16 + (lane >> 4) * 8;
                    ldsm_x4t(vh4[cur ^ 1], bVh + ro);
                    ldsm_x4t(vl4[cur ^ 1], bVl + ro);
                }
                uint32_t vhe[2] = {vh4[cur][0], vh4[cur][1]}, vho[2] = {vh4[cur][2], vh4[cur][3]};
                uint32_t vle[2] = {vl4[cur][0], vl4[cur][1]}, vlo[2] = {vl4[cur][2], vl4[cur][3]};
                mma16816h(oacc[2*nt2],   ph, vhe);
                mma16816h(oacc[2*nt2+1], ph, vho);
                mma16816h(oacc[2*nt2],   ph, vle);
                mma16816h(oacc[2*nt2+1], ph, vlo);
                mma16816h(oacc[2*nt2],   pl, vhe);
                mma16816h(oacc[2*nt2+1], pl, vho);
            }
        }
    }

    float inv0 = __fdividef(1.f, l_i[0]);
    float inv1 = __fdividef(1.f, l_i[1]);
    size_t r0 = (size_t)(b * SS + s0 + m0 + g) * DD + h * 64;
    size_t r8 = r0 + (size_t)8 * DD;
#pragma unroll
    for (int nt = 0; nt < 8; ++nt) {
        int col = nt * 8 + 2 * t4;
        uint32_t hh, ll;
        split2h(oacc[nt][0] * inv0, oacc[nt][1] * inv0, hh, ll);
        *(uint32_t*)&Oh[r0 + col] = hh; *(uint32_t*)&Ol[r0 + col] = ll;
        split2h(oacc[nt][2] * inv1, oacc[nt][3] * inv1, hh, ll);
        *(uint32_t*)&Oh[r8 + col] = hh; *(uint32_t*)&Ol[r8 + col] = ll;
    }
}

// ---------------------------------------------------------------------------
extern "C" void kernel_launch(void* const* d_in, const int* in_sizes, int n_in,
                              void* d_out, int out_size)
{
    const float* queries = (const float*)d_in[0];
    const float* keys    = (const float*)d_in[1];
    const float* values  = (const float*)d_in[2];
    const int*   mask    = (const int*)  d_in[3];
    const float* Wq = (const float*)d_in[4];
    const float* Wk = (const float*)d_in[5];
    const float* Wv = (const float*)d_in[6];
    const float* Wo = (const float*)d_in[7];
    float* out = (float*)d_out;

    __half *xqh,*xql,*xkh,*xkl,*xvh,*xvl, *wqkvh,*woh;
    __half *qkvh,*qkvl,*oh,*ol;
    uint32_t* mb;
    cudaGetSymbolAddress((void**)&xqh, g_xqh);   cudaGetSymbolAddress((void**)&xql, g_xql);
    cudaGetSymbolAddress((void**)&xkh, g_xkh);   cudaGetSymbolAddress((void**)&xkl, g_xkl);
    cudaGetSymbolAddress((void**)&xvh, g_xvh);   cudaGetSymbolAddress((void**)&xvl, g_xvl);
    cudaGetSymbolAddress((void**)&wqkvh, g_wqkvh);
    cudaGetSymbolAddress((void**)&woh, g_woh);
    cudaGetSymbolAddress((void**)&qkvh, g_qkvh); cudaGetSymbolAddress((void**)&qkvl, g_qkvl);
    cudaGetSymbolAddress((void**)&oh, g_oh);     cudaGetSymbolAddress((void**)&ol, g_ol);
    cudaGetSymbolAddress((void**)&mb, g_mbits);

    const int GEMM_SMEM = 2 * GSTAGE * (int)sizeof(__half);                 // 61440
    cudaFuncSetAttribute(gemm_mma, cudaFuncAttributeMaxDynamicSharedMemorySize, GEMM_SMEM);
    const int ATTN_SMEM = (2 * 128 * TS + 2 * A_KVSZ) * (int)sizeof(__half); // 110592
    cudaFuncSetAttribute(attn_tc, cudaFuncAttributeMaxDynamicSharedMemorySize, ATTN_SMEM);

    const int n4i = MTOK * DD / 4, n4w = DD * DD / 4;
    split3_kernel<<<dim3(n4i / 1024, 3), 256>>>(
        (const float4*)queries, (const float4*)keys, (const float4*)values,
        (uint2*)xqh, (uint2*)xql, (uint2*)xkh, (uint2*)xkl, (uint2*)xvh, (uint2*)xvl, n4i);
    splitw_kernel<<<dim3(n4w / 256, 4), 256>>>(
        (const float4*)Wq, (const float4*)Wk, (const float4*)Wv, (const float4*)Wo,
        (uint2*)wqkvh, (uint2*)woh, n4w);
    maskbits_kernel<<<(int)((size_t)BB * SS * SS / 128 / 8), 256>>>(mask, mb);

    // merged QKV projection (Wq pre-scaled): C = [MTOK, 3072] split fp16
    gemm_mma<<<dim3(NQKV / 128, MTOK / 128), 256, GEMM_SMEM>>>(
        xqh, xql, xkh, xkl, xvh, xvl, wqkvh,
        nullptr, qkvh, qkvl, NQKV, DD, 1);

    attn_tc<<<dim3(SS / 128, HH, BB), 256, ATTN_SMEM>>>(qkvh, qkvl, mb, oh, ol);

    // output projection
    gemm_mma<<<dim3(DD / 128, MTOK / 128), 256, GEMM_SMEM>>>(
        oh, ol, oh, ol, oh, ol, woh,
        out, nullptr, nullptr, DD, DD, 0);
}

// round 16
// speedup vs baseline: 1.4603x; 1.1618x over previous
#include <cuda_runtime.h>
#include <cuda_fp16.h>
#include <cstdint>
#include <cstddef>

#define BB 4
#define SS 2048
#define DD 1024
#define HH 16
#define MTOK (BB*SS)
#define NQKV (3*DD)
#define QSCALE 0.1803368801111204f   // 0.125 * log2(e)

// ---------------- scratch (__device__ globals; allocs forbidden) ----------
__device__ __half g_xqh[MTOK*DD], g_xql[MTOK*DD];
__device__ __half g_xkh[MTOK*DD], g_xkl[MTOK*DD];
__device__ __half g_xvh[MTOK*DD], g_xvl[MTOK*DD];
__device__ __half g_wqkvh[3*DD*DD];
__device__ __half g_woh[DD*DD];
__device__ __half g_qkvh[(size_t)MTOK*NQKV], g_qkvl[(size_t)MTOK*NQKV];
__device__ __half g_oh[MTOK*DD], g_ol[MTOK*DD];
__device__ uint32_t g_mbits[(size_t)BB*SS*(SS/32)];

// ---------------- helpers --------------------------------------------------
__device__ __forceinline__ uint32_t smem_u32(const void* p) {
    return (uint32_t)__cvta_generic_to_shared(p);
}
__device__ __forceinline__ void mma16816h(float* c, const uint32_t* a, const uint32_t* b) {
    asm volatile(
        "mma.sync.aligned.m16n8k16.row.col.f32.f16.f16.f32 "
        "{%0,%1,%2,%3},{%4,%5,%6,%7},{%8,%9},{%0,%1,%2,%3};"
        : "+f"(c[0]), "+f"(c[1]), "+f"(c[2]), "+f"(c[3])
        : "r"(a[0]), "r"(a[1]), "r"(a[2]), "r"(a[3]), "r"(b[0]), "r"(b[1]));
}
__device__ __forceinline__ void ldsm_x4(uint32_t* r, const void* p) {
    uint32_t a = smem_u32(p);
    asm volatile("ldmatrix.sync.aligned.m8n8.x4.shared.b16 {%0,%1,%2,%3},[%4];"
                 : "=r"(r[0]), "=r"(r[1]), "=r"(r[2]), "=r"(r[3]) : "r"(a));
}
__device__ __forceinline__ void ldsm_x4t(uint32_t* r, const void* p) {
    uint32_t a = smem_u32(p);
    asm volatile("ldmatrix.sync.aligned.m8n8.x4.trans.shared.b16 {%0,%1,%2,%3},[%4];"
                 : "=r"(r[0]), "=r"(r[1]), "=r"(r[2]), "=r"(r[3]) : "r"(a));
}
// fp16 2-way split: x = hi + lo, hi = fp16(x)
__device__ __forceinline__ void split2h(float f0, float f1, uint32_t& hi, uint32_t& lo) {
    __half2 h = __floats2half2_rn(f0, f1);
    float r0 = f0 - __half2float(__low2half(h));
    float r1 = f1 - __half2float(__high2half(h));
    hi = *reinterpret_cast<uint32_t*>(&h);
    __half2 l = __floats2half2_rn(r0, r1);
    lo = *reinterpret_cast<uint32_t*>(&l);
}
__device__ __forceinline__ void cp16(void* s, const void* g) {
    uint32_t sa = smem_u32(s);
    asm volatile("cp.async.cg.shared.global [%0], [%1], 16;" :: "r"(sa), "l"(g));
}
#define CP_COMMIT() asm volatile("cp.async.commit_group;" ::: "memory")
#define CP_WAIT(n)  asm volatile("cp.async.wait_group %0;" :: "n"(n) : "memory")

// ---------------- prepass kernels ------------------------------------------
__global__ void split3_kernel(const float4* __restrict__ x0, const float4* __restrict__ x1,
                              const float4* __restrict__ x2,
                              uint2* __restrict__ h0, uint2* __restrict__ l0,
                              uint2* __restrict__ h1, uint2* __restrict__ l1,
                              uint2* __restrict__ h2, uint2* __restrict__ l2, int n4) {
    int base = blockIdx.x * 1024 + threadIdx.x;
    const float4* x = (blockIdx.y == 0) ? x0 : (blockIdx.y == 1) ? x1 : x2;
    uint2* h = (blockIdx.y == 0) ? h0 : (blockIdx.y == 1) ? h1 : h2;
    uint2* l = (blockIdx.y == 0) ? l0 : (blockIdx.y == 1) ? l1 : l2;
    float4 v[4];
#pragma unroll
    for (int r = 0; r < 4; ++r) v[r] = x[base + r * 256];
#pragma unroll
    for (int r = 0; r < 4; ++r) {
        uint2 hh, ll;
        split2h(v[r].x, v[r].y, hh.x, ll.x);
        split2h(v[r].z, v[r].w, hh.y, ll.y);
        h[base + r * 256] = hh;
        l[base + r * 256] = ll;
    }
}
__global__ void splitw_kernel(const float4* __restrict__ wq, const float4* __restrict__ wk,
                              const float4* __restrict__ wv, const float4* __restrict__ wo,
                              uint2* __restrict__ qkvh, uint2* __restrict__ woh, int n4) {
    int i = blockIdx.x * 256 + threadIdx.x;
    if (i >= n4) return;
    int y = blockIdx.y;
    const float4* src = (y == 0) ? wq : (y == 1) ? wk : (y == 2) ? wv : wo;
    float4 v = src[i];
    if (y == 0) { v.x *= QSCALE; v.y *= QSCALE; v.z *= QSCALE; v.w *= QSCALE; }
    __half2 a = __floats2half2_rn(v.x, v.y);
    __half2 b = __floats2half2_rn(v.z, v.w);
    uint2 hh;
    hh.x = *reinterpret_cast<uint32_t*>(&a);
    hh.y = *reinterpret_cast<uint32_t*>(&b);
    uint2* h = (y < 3) ? (qkvh + (size_t)y * n4) : woh;
    h[i] = hh;
}
__global__ void maskbits_kernel(const int* __restrict__ m, uint32_t* __restrict__ bits) {
    size_t w = (size_t)blockIdx.x * 8 + (threadIdx.x >> 5);
    int lane = threadIdx.x & 31;
    const int* p = m + w * 128;
    int v0 = p[lane], v1 = p[lane + 32], v2 = p[lane + 64], v3 = p[lane + 96];
    uint32_t b0 = __ballot_sync(0xffffffffu, v0 != 0);
    uint32_t b1 = __ballot_sync(0xffffffffu, v1 != 0);
    uint32_t b2 = __ballot_sync(0xffffffffu, v2 != 0);
    uint32_t b3 = __ballot_sync(0xffffffffu, v3 != 0);
    if (lane == 0) { bits[w*4] = b0; bits[w*4+1] = b1; bits[w*4+2] = b2; bits[w*4+3] = b3; }
}

// ---------------- GEMM: C = (Ah+Al) * Wh^T, fp16, 2 mmas (R14 proven) -------
#define GST 40
#define G_AH 0
#define G_AL (128*GST)
#define G_WH (2*128*GST)
#define GSTAGE (3*128*GST)

__global__ __launch_bounds__(256, 2) void gemm_mma(
    const __half* __restrict__ A0h, const __half* __restrict__ A0l,
    const __half* __restrict__ A1h, const __half* __restrict__ A1l,
    const __half* __restrict__ A2h, const __half* __restrict__ A2l,
    const __half* __restrict__ Wh,
    float* __restrict__ Cf, __half* __restrict__ Ch, __half* __restrict__ Cl,
    int N, int K, int split_out)
{
    extern __shared__ __align__(16) __half sg[];

    const int tid = threadIdx.x, lane = tid & 31, w = tid >> 5;
    const int g = lane >> 2, t4 = lane & 3, l15 = lane & 15;
    const int m0 = (w >> 2) * 64, n0 = (w & 3) * 32;
    const int bm = blockIdx.y * 128, bn = blockIdx.x * 128;

    const int sel = bn >> 10;
    const __half* Ah = (sel == 0) ? A0h : (sel == 1) ? A1h : A2h;
    const __half* Al = (sel == 0) ? A0l : (sel == 1) ? A1l : A2l;

    const __half* pAh = Ah + (size_t)bm * K;
    const __half* pAl = Al + (size_t)bm * K;
    const __half* pWh = Wh + (size_t)bn * K;

    auto stage = [&](int buf, int k0) {
        __half* st = sg + buf * GSTAGE;
#pragma unroll
        for (int it = 0; it < 6; ++it) {
            int c = it * 256 + tid;
            int mat = c >> 9, r = (c >> 2) & 127, u = c & 3;
            const __half* src =
                (mat == 0 ? pAh : mat == 1 ? pAl : pWh) + (size_t)r * K + k0 + u * 8;
            cp16(st + mat * (128 * GST) + r * GST + u * 8, src);
        }
    };

    float acc[4][4][4];
#pragma unroll
    for (int i = 0; i < 4; ++i)
#pragma unroll
        for (int j = 0; j < 4; ++j)
#pragma unroll
            for (int c = 0; c < 4; ++c) acc[i][j][c] = 0.f;

    const int NST = K / 32;
    stage(0, 0); CP_COMMIT();

    for (int kt = 0; kt < NST; ++kt) {
        const int buf = kt & 1;
        if (kt + 1 < NST) { stage(buf ^ 1, (kt + 1) * 32); CP_COMMIT(); CP_WAIT(1); }
        else CP_WAIT(0);
        __syncthreads();

        const __half* st = sg + buf * GSTAGE;
#pragma unroll
        for (int ks = 0; ks < 32; ks += 16) {
            uint32_t wh[2][4];
            {
                const int ro0 = (n0 + l15) * GST + ks + (lane >> 4) * 8;
                const int ro1 = (n0 + 16 + l15) * GST + ks + (lane >> 4) * 8;
                ldsm_x4(wh[0], st + G_WH + ro0);
                ldsm_x4(wh[1], st + G_WH + ro1);
            }
            uint32_t ah[2][4], al[2][4];
            {
                const int ro = (m0 + l15) * GST + ks + (lane >> 4) * 8;
                ldsm_x4(ah[0], st + G_AH + ro);
                ldsm_x4(al[0], st + G_AL + ro);
            }
#pragma unroll
            for (int mt = 0; mt < 4; ++mt) {
                const int cur = mt & 1;
                if (mt < 3) {
                    const int ro = (m0 + (mt + 1) * 16 + l15) * GST + ks + (lane >> 4) * 8;
                    ldsm_x4(ah[cur ^ 1], st + G_AH + ro);
                    ldsm_x4(al[cur ^ 1], st + G_AL + ro);
                }
#pragma unroll
                for (int nn = 0; nn < 2; ++nn) {
                    uint32_t bhe[2] = {wh[nn][0], wh[nn][2]}, bho[2] = {wh[nn][1], wh[nn][3]};
                    mma16816h(acc[mt][2*nn],   ah[cur], bhe);
                    mma16816h(acc[mt][2*nn+1], ah[cur], bho);
                    mma16816h(acc[mt][2*nn],   al[cur], bhe);
                    mma16816h(acc[mt][2*nn+1], al[cur], bho);
                }
            }
        }
        __syncthreads();
    }

#pragma unroll
    for (int mt = 0; mt < 4; ++mt)
#pragma unroll
        for (int nt = 0; nt < 4; ++nt) {
            int row = bm + m0 + mt * 16 + g;
            int col = bn + n0 + nt * 8 + 2 * t4;
            if (split_out) {
                uint32_t hh, ll;
                split2h(acc[mt][nt][0], acc[mt][nt][1], hh, ll);
                *(uint32_t*)&Ch[(size_t)row * N + col] = hh;
                *(uint32_t*)&Cl[(size_t)row * N + col] = ll;
                split2h(acc[mt][nt][2], acc[mt][nt][3], hh, ll);
                *(uint32_t*)&Ch[(size_t)(row + 8) * N + col] = hh;
                *(uint32_t*)&Cl[(size_t)(row + 8) * N + col] = ll;
            } else {
                *(float2*)(Cf + (size_t)row * N + col) =
                    make_float2(acc[mt][nt][0], acc[mt][nt][1]);
                *(float2*)(Cf + (size_t)(row + 8) * N + col) =
                    make_float2(acc[mt][nt][2], acc[mt][nt][3]);
            }
        }
}

// ---------------- attention: 128-query tile, 8 warps, Kh/Vh only ------------
#define TS 72
#define A_QH 0
#define A_QL (128*TS)
#define A_KV (2*128*TS)
#define A_KVSZ (2*64*TS)     // Kh, Vh per buffer

__global__ __launch_bounds__(256) void attn_tc(
    const __half* __restrict__ QKVh, const __half* __restrict__ QKVl,
    const uint32_t* __restrict__ mbits,
    __half* __restrict__ Oh, __half* __restrict__ Ol)
{
    extern __shared__ __align__(16) __half sm[];

    const int b = blockIdx.z, h = blockIdx.y, s0 = blockIdx.x * 128;
    const int tid = threadIdx.x, lane = tid & 31, w = tid >> 5;
    const int g = lane >> 2, t4 = lane & 3;
    const int m0 = w * 16, l15 = lane & 15;

    const __half* qhp = QKVh + (size_t)(b * SS + s0) * NQKV + h * 64;
    const __half* qlp = QKVl + (size_t)(b * SS + s0) * NQKV + h * 64;
#pragma unroll
    for (int it = 0; it < 8; ++it) {
        int c = it * 256 + tid;
        int r = (c & 1023) >> 3, u = c & 7;
        if (c < 1024) cp16(&sm[A_QH + r * TS + u * 8], qhp + (size_t)r * NQKV + u * 8);
        else          cp16(&sm[A_QL + r * TS + u * 8], qlp + (size_t)r * NQKV + u * 8);
    }

    const __half* khp = QKVh + (size_t)(b * SS) * NQKV + DD + h * 64;
    const __half* vhp = QKVh + (size_t)(b * SS) * NQKV + 2 * DD + h * 64;

    auto stageKV = [&](int buf, int t0) {   // Kh + Vh only: 1024 cp16
        __half* st = sm + A_KV + buf * A_KVSZ;
#pragma unroll
        for (int it = 0; it < 4; ++it) {
            int c = it * 256 + tid;          // 0..1023
            int mat = c >> 9, r = (c >> 3) & 63, u = c & 7;
            const __half* src = (mat == 0 ? khp : vhp) + (size_t)(t0 + r) * NQKV + u * 8;
            cp16(st + mat * (64 * TS) + r * TS + u * 8, src);
        }
    };

    stageKV(0, 0);
    CP_COMMIT();

    float m_i[2] = {-1e30f, -1e30f}, l_i[2] = {0.f, 0.f};
    float oacc[8][4];
#pragma unroll
    for (int nt = 0; nt < 8; ++nt)
#pragma unroll
        for (int c = 0; c < 4; ++c) oacc[nt][c] = 0.f;

    const uint32_t* mb0 = mbits + ((size_t)b * SS + s0 + m0 + g) * (SS / 32);
    const uint32_t* mb8 = mb0 + 8 * (SS / 32);

    for (int i = 0; i < SS / 64; ++i) {
        const int t0 = i * 64, buf = i & 1;
        __syncthreads();
        if (i + 1 < SS / 64) { stageKV(buf ^ 1, t0 + 64); CP_COMMIT(); CP_WAIT(1); }
        else CP_WAIT(0);
        __syncthreads();

        const __half* bKh = sm + A_KV + buf * A_KVSZ;
        const __half* bVh = bKh + 64 * TS;

        // ---- S = (Qh+Ql) Kh^T : 2 mmas per fragment pair ----
        float sc[8][4];
#pragma unroll
        for (int nt = 0; nt < 8; ++nt)
#pragma unroll
            for (int c = 0; c < 4; ++c) sc[nt][c] = 0.f;

#pragma unroll
        for (int ks = 0; ks < 64; ks += 16) {
            uint32_t qfh[4], qfl[4];
            const int qo = (m0 + l15) * TS + ks + (lane >> 4) * 8;
            ldsm_x4(qfh, &sm[A_QH + qo]);
            ldsm_x4(qfl, &sm[A_QL + qo]);

            uint32_t kh4[2][4];
            {
                const int ro = (l15) * TS + ks + (lane >> 4) * 8;
                ldsm_x4(kh4[0], bKh + ro);
            }
#pragma unroll
            for (int nt2 = 0; nt2 < 4; ++nt2) {
                const int cur = nt2 & 1;
                if (nt2 < 3) {
                    const int ro = ((nt2 + 1) * 16 + l15) * TS + ks + (lane >> 4) * 8;
                    ldsm_x4(kh4[cur ^ 1], bKh + ro);
                }
                uint32_t bhe[2] = {kh4[cur][0], kh4[cur][2]}, bho[2] = {kh4[cur][1], kh4[cur][3]};
                mma16816h(sc[2*nt2],   qfh, bhe);
                mma16816h(sc[2*nt2+1], qfh, bho);
                mma16816h(sc[2*nt2],   qfl, bhe);
                mma16816h(sc[2*nt2+1], qfl, bho);
            }
        }

        uint32_t wa0 = mb0[t0 >> 5], wb0 = mb0[(t0 >> 5) + 1];
        uint32_t wa8 = mb8[t0 >> 5], wb8 = mb8[(t0 >> 5) + 1];
        if ((wa0 & wb0 & wa8 & wb8) != 0xffffffffu) {
#pragma unroll
            for (int nt = 0; nt < 8; ++nt) {
                int c = nt * 8 + 2 * t4;
                uint32_t s0w = (c & 32) ? wb0 : wa0;
                uint32_t s8w = (c & 32) ? wb8 : wa8;
                int sh = c & 31;
                if (!((s0w >> sh) & 1))       sc[nt][0] = -1e10f;
                if (!((s0w >> (sh + 1)) & 1)) sc[nt][1] = -1e10f;
                if (!((s8w >> sh) & 1))       sc[nt][2] = -1e10f;
                if (!((s8w >> (sh + 1)) & 1)) sc[nt][3] = -1e10f;
            }
        }

        float mx0 = -1e30f, mx1 = -1e30f;
#pragma unroll
        for (int nt = 0; nt < 8; ++nt) {
            mx0 = fmaxf(mx0, fmaxf(sc[nt][0], sc[nt][1]));
            mx1 = fmaxf(mx1, fmaxf(sc[nt][2], sc[nt][3]));
        }
        mx0 = fmaxf(mx0, __shfl_xor_sync(0xffffffffu, mx0, 1));
        mx0 = fmaxf(mx0, __shfl_xor_sync(0xffffffffu, mx0, 2));
        mx1 = fmaxf(mx1, __shfl_xor_sync(0xffffffffu, mx1, 1));
        mx1 = fmaxf(mx1, __shfl_xor_sync(0xffffffffu, mx1, 2));

        float mn0 = fmaxf(m_i[0], mx0), mn1 = fmaxf(m_i[1], mx1);
        float corr0 = exp2f(m_i[0] - mn0), corr1 = exp2f(m_i[1] - mn1);
        m_i[0] = mn0; m_i[1] = mn1;

        float sum0 = 0.f, sum1 = 0.f;
#pragma unroll
        for (int nt = 0; nt < 8; ++nt) {
            sc[nt][0] = exp2f(sc[nt][0] - mn0);
            sc[nt][1] = exp2f(sc[nt][1] - mn0);
            sc[nt][2] = exp2f(sc[nt][2] - mn1);
            sc[nt][3] = exp2f(sc[nt][3] - mn1);
            sum0 += sc[nt][0] + sc[nt][1];
            sum1 += sc[nt][2] + sc[nt][3];
        }
        sum0 += __shfl_xor_sync(0xffffffffu, sum0, 1);
        sum0 += __shfl_xor_sync(0xffffffffu, sum0, 2);
        sum1 += __shfl_xor_sync(0xffffffffu, sum1, 1);
        sum1 += __shfl_xor_sync(0xffffffffu, sum1, 2);
        l_i[0] = l_i[0] * corr0 + sum0;
        l_i[1] = l_i[1] * corr1 + sum1;
#pragma unroll
        for (int nt = 0; nt < 8; ++nt) {
            oacc[nt][0] *= corr0; oacc[nt][1] *= corr0;
            oacc[nt][2] *= corr1; oacc[nt][3] *= corr1;
        }

        // ---- O += (Ph+Pl) Vh : 2 mmas per fragment pair ----
#pragma unroll
        for (int j = 0; j < 4; ++j) {
            uint32_t ph[4], pl[4];
            split2h(sc[2*j][0],   sc[2*j][1],   ph[0], pl[0]);
            split2h(sc[2*j][2],   sc[2*j][3],   ph[1], pl[1]);
            split2h(sc[2*j+1][0], sc[2*j+1][1], ph[2], pl[2]);
            split2h(sc[2*j+1][2], sc[2*j+1][3], ph[3], pl[3]);

            uint32_t vh4[2][4];
            {
                const int ro = (j * 16 + l15) * TS + (lane >> 4) * 8;
                ldsm_x4t(vh4[0], bVh + ro);
            }
#pragma unroll
            for (int nt2 = 0; nt2 < 4; ++nt2) {
                const int cur = nt2 & 1;
                if (nt2 < 3) {
                    const int ro = (j * 16 + l15) * TS + (nt2 + 1) * 16 + (lane >> 4) * 8;
                    ldsm_x4t(vh4[cur ^ 1], bVh + ro);
                }
                uint32_t vhe[2] = {vh4[cur][0], vh4[cur][1]}, vho[2] = {vh4[cur][2], vh4[cur][3]};
                mma16816h(oacc[2*nt2],   ph, vhe);
                mma16816h(oacc[2*nt2+1], ph, vho);
                mma16816h(oacc[2*nt2],   pl, vhe);
                mma16816h(oacc[2*nt2+1], pl, vho);
            }
        }
    }

    float inv0 = __fdividef(1.f, l_i[0]);
    float inv1 = __fdividef(1.f, l_i[1]);
    size_t r0 = (size_t)(b * SS + s0 + m0 + g) * DD + h * 64;
    size_t r8 = r0 + (size_t)8 * DD;
#pragma unroll
    for (int nt = 0; nt < 8; ++nt) {
        int col = nt * 8 + 2 * t4;
        uint32_t hh, ll;
        split2h(oacc[nt][0] * inv0, oacc[nt][1] * inv0, hh, ll);
        *(uint32_t*)&Oh[r0 + col] = hh; *(uint32_t*)&Ol[r0 + col] = ll;
        split2h(oacc[nt][2] * inv1, oacc[nt][3] * inv1, hh, ll);
        *(uint32_t*)&Oh[r8 + col] = hh; *(uint32_t*)&Ol[r8 + col] = ll;
    }
}

// ---------------------------------------------------------------------------
extern "C" void kernel_launch(void* const* d_in, const int* in_sizes, int n_in,
                              void* d_out, int out_size)
{
    const float* queries = (const float*)d_in[0];
    const float* keys    = (const float*)d_in[1];
    const float* values  = (const float*)d_in[2];
    const int*   mask    = (const int*)  d_in[3];
    const float* Wq = (const float*)d_in[4];
    const float* Wk = (const float*)d_in[5];
    const float* Wv = (const float*)d_in[6];
    const float* Wo = (const float*)d_in[7];
    float* out = (float*)d_out;

    __half *xqh,*xql,*xkh,*xkl,*xvh,*xvl, *wqkvh,*woh;
    __half *qkvh,*qkvl,*oh,*ol;
    uint32_t* mb;
    cudaGetSymbolAddress((void**)&xqh, g_xqh);   cudaGetSymbolAddress((void**)&xql, g_xql);
    cudaGetSymbolAddress((void**)&xkh, g_xkh);   cudaGetSymbolAddress((void**)&xkl, g_xkl);
    cudaGetSymbolAddress((void**)&xvh, g_xvh);   cudaGetSymbolAddress((void**)&xvl, g_xvl);
    cudaGetSymbolAddress((void**)&wqkvh, g_wqkvh);
    cudaGetSymbolAddress((void**)&woh, g_woh);
    cudaGetSymbolAddress((void**)&qkvh, g_qkvh); cudaGetSymbolAddress((void**)&qkvl, g_qkvl);
    cudaGetSymbolAddress((void**)&oh, g_oh);     cudaGetSymbolAddress((void**)&ol, g_ol);
    cudaGetSymbolAddress((void**)&mb, g_mbits);

    const int GEMM_SMEM = 2 * GSTAGE * (int)sizeof(__half);                  // 61440
    cudaFuncSetAttribute(gemm_mma, cudaFuncAttributeMaxDynamicSharedMemorySize, GEMM_SMEM);
    const int ATTN_SMEM = (2 * 128 * TS + 2 * A_KVSZ) * (int)sizeof(__half); // 73728
    cudaFuncSetAttribute(attn_tc, cudaFuncAttributeMaxDynamicSharedMemorySize, ATTN_SMEM);

    const int n4i = MTOK * DD / 4, n4w = DD * DD / 4;
    split3_kernel<<<dim3(n4i / 1024, 3), 256>>>(
        (const float4*)queries, (const float4*)keys, (const float4*)values,
        (uint2*)xqh, (uint2*)xql, (uint2*)xkh, (uint2*)xkl, (uint2*)xvh, (uint2*)xvl, n4i);
    splitw_kernel<<<dim3(n4w / 256, 4), 256>>>(
        (const float4*)Wq, (const float4*)Wk, (const float4*)Wv, (const float4*)Wo,
        (uint2*)wqkvh, (uint2*)woh, n4w);
    maskbits_kernel<<<(int)((size_t)BB * SS * SS / 128 / 8), 256>>>(mask, mb);

    gemm_mma<<<dim3(NQKV / 128, MTOK / 128), 256, GEMM_SMEM>>>(
        xqh, xql, xkh, xkl, xvh, xvl, wqkvh,
        nullptr, qkvh, qkvl, NQKV, DD, 1);

    attn_tc<<<dim3(SS / 128, HH, BB), 256, ATTN_SMEM>>>(qkvh, qkvl, mb, oh, ol);

    gemm_mma<<<dim3(DD / 128, MTOK / 128), 256, GEMM_SMEM>>>(
        oh, ol, oh, ol, oh, ol, woh,
        out, nullptr, nullptr, DD, DD, 0);
}